// round 7
// baseline (speedup 1.0000x reference)
#include <cuda_runtime.h>
#include <math.h>

#define NTOK 401
#define NPT  400
#define DIMM 512
#define NHEAD 8
#define HDIM 64
#define QKV3 1536
#define CPBH 512
#define NPAIR (NTOK*NTOK)
#define TABN 8192
#define PI_F 3.14159265358979323846f
#define FLAG_RELU 1
#define FLAG_ADD  2

// ---------------- scratch (alloc-free, __device__ globals) ----------------
__device__ float  g_h[NTOK*DIMM];          // residual stream
__device__ float  g_ln[NTOK*DIMM];         // layernorm output
__device__ float  g_qkv[NTOK*QKV3];        // fused qkv
__device__ float  g_attn[NHEAD*NTOK*NTOK]; // attention logits / probs (5.1 MB)
__device__ float  g_ao[NTOK*DIMM];         // attention output (pre-proj)
__device__ float  g_angpos[NPAIR];         // table position per pair (shared by layers)
__device__ float  g_coords[NTOK*2];
__device__ float  g_table0[(TABN+4)*8];    // layer-1 bias table
__device__ float  g_table1[(TABN+4)*8];    // layer-2 bias table

// ---------------- small helpers ----------------
__device__ __forceinline__ float2 blockReduce2_256(float a, float b) {
    __shared__ float sa[8], sb[8];
    __syncthreads();
    #pragma unroll
    for (int o = 16; o > 0; o >>= 1) {
        a += __shfl_xor_sync(0xffffffffu, a, o);
        b += __shfl_xor_sync(0xffffffffu, b, o);
    }
    int w = threadIdx.x >> 5;
    if ((threadIdx.x & 31) == 0) { sa[w] = a; sb[w] = b; }
    __syncthreads();
    a = sa[0]+sa[1]+sa[2]+sa[3]+sa[4]+sa[5]+sa[6]+sa[7];
    b = sb[0]+sb[1]+sb[2]+sb[3]+sb[4]+sb[5]+sb[6]+sb[7];
    return make_float2(a, b);
}

// ---------------- setup: CLS row + coords (CLS coord = 0) ----------------
__global__ void setup_kernel(const float* __restrict__ cls,
                             const float* __restrict__ coords) {
    int t = blockIdx.x*blockDim.x + threadIdx.x;
    if (t < DIMM)  g_h[t] = cls[t];
    if (t < 2)     g_coords[t] = 0.f;
    if (t < NPT*2) g_coords[2+t] = coords[t];
}

// ---------------- per-pair angle table position ----------------
__global__ void angpos_kernel() {
    int p = blockIdx.x*blockDim.x + threadIdx.x;
    if (p >= NPAIR) return;
    int i = p / NTOK, j = p - i*NTOK;
    float pos;
    if (i == j) {
        pos = (float)(TABN + 1);           // diag: dir = (0,0) special row
    } else {
        float dx = g_coords[2*i]   - g_coords[2*j];
        float dy = g_coords[2*i+1] - g_coords[2*j+1];
        float th = atan2f(dy, dx);
        pos = (th + PI_F) * ((float)TABN / (2.0f*PI_F));
        pos = fminf(fmaxf(pos, 0.f), (float)TABN);
    }
    g_angpos[p] = pos;
}

// ---------------- build CPB bias table ----------------
// 256 threads = 8 warps (channel groups of 64) x 32 lanes (entries).
// All lanes in a warp read the SAME channel -> broadcast LDS, conflict-free.
__global__ void __launch_bounds__(256) cpb_table_kernel(
        const float* __restrict__ w1, const float* __restrict__ b1,
        const float* __restrict__ w2, const float* __restrict__ b2,
        float* __restrict__ out) {
    __shared__ float swx[CPBH], swy[CPBH], sbb[CPBH];
    __shared__ __align__(16) float sw2[CPBH*8];
    __shared__ float sred[8][32][9];       // padded: 9 coprime 32 -> no conflicts
    int t = threadIdx.x;
    for (int c = t; c < CPBH; c += 256) {
        swx[c] = w1[c]; swy[c] = w1[CPBH + c]; sbb[c] = b1[c];
    }
    for (int c = t; c < CPBH*2; c += 256)
        *(float4*)(sw2 + c*4) = *(const float4*)(w2 + c*4);
    __syncthreads();

    int e = t & 31;                     // entry (lane)
    int w = t >> 5;                     // warp = channel group
    int idx = blockIdx.x*32 + e;
    float ux = 0.f, uy = 0.f;
    if (idx <= TABN) {
        float th = -PI_F + (2.0f*PI_F) * ((float)idx / (float)TABN);
        sincosf(th, &uy, &ux);
    }
    float acc[8] = {0.f,0.f,0.f,0.f,0.f,0.f,0.f,0.f};
    int c0 = w << 6;
    #pragma unroll 8
    for (int cc = 0; cc < 64; cc++) {
        int c = c0 + cc;
        float hv = fmaf(ux, swx[c], fmaf(uy, swy[c], sbb[c]));  // broadcast
        hv = fmaxf(hv, 0.f);
        float4 wa = *(const float4*)(sw2 + (c<<3));             // broadcast
        float4 wb = *(const float4*)(sw2 + (c<<3) + 4);         // broadcast
        acc[0] = fmaf(hv, wa.x, acc[0]);
        acc[1] = fmaf(hv, wa.y, acc[1]);
        acc[2] = fmaf(hv, wa.z, acc[2]);
        acc[3] = fmaf(hv, wa.w, acc[3]);
        acc[4] = fmaf(hv, wb.x, acc[4]);
        acc[5] = fmaf(hv, wb.y, acc[5]);
        acc[6] = fmaf(hv, wb.z, acc[6]);
        acc[7] = fmaf(hv, wb.w, acc[7]);
    }
    #pragma unroll
    for (int k = 0; k < 8; k++) sred[w][e][k] = acc[k];
    __syncthreads();

    int re = t >> 3, rk = t & 7;
    float s = 0.f;
    #pragma unroll
    for (int ww = 0; ww < 8; ww++) s += sred[ww][re][rk];
    int ridx = blockIdx.x*32 + re;
    if (ridx <= TABN + 2) {
        float v = (ridx == TABN + 2) ? 0.f : s + b2[rk];
        out[(size_t)ridx*8 + rk] = v;
    }
}

// ---------------- 32x64-tile fp32 GEMM, 128 threads, 4x4/thread ----------
// C = A[M,K](lda) @ B[K,N](ldb) + bias, opt relu/add. K%16==0, N%64==0.
__global__ void __launch_bounds__(128) gemm_kernel(
        const float* __restrict__ A, int lda,
        const float* __restrict__ B, int ldb,
        const float* __restrict__ bias,
        float* __restrict__ C, int ldc,
        int M, int N, int K, int flags) {
    __shared__ __align__(16) float As[2][16][36];
    __shared__ __align__(16) float Bs[2][16][68];
    int t  = threadIdx.x;
    int m0 = blockIdx.y << 5, n0 = blockIdx.x << 6;
    int arow = t >> 2, acol = (t & 3) << 2;        // A tile 32x16, float4/thread
    int brow = t >> 3, bcol = (t & 7) << 3;        // B tile 16x64, 2 float4/thread
    int tx = t & 15, ty = t >> 4;                  // out: 4 rows (ty) x 4 cols (tx)
    float acc[4][4] = {};

    bool aval = (m0 + arow) < M;
    const float* Aptr = A + (size_t)(m0 + arow)*lda + acol;
    const float* Bptr = B + (size_t)brow*ldb + n0 + bcol;

    float4 ra  = aval ? *(const float4*)Aptr : make_float4(0.f,0.f,0.f,0.f);
    float4 rb0 = *(const float4*)Bptr;
    float4 rb1 = *(const float4*)(Bptr + 4);
    int buf = 0;
    As[0][acol  ][arow] = ra.x; As[0][acol+1][arow] = ra.y;
    As[0][acol+2][arow] = ra.z; As[0][acol+3][arow] = ra.w;
    *(float4*)&Bs[0][brow][bcol]   = rb0;
    *(float4*)&Bs[0][brow][bcol+4] = rb1;
    __syncthreads();

    for (int k0 = 16; ; k0 += 16) {
        bool more = (k0 < K);
        if (more) {
            ra  = aval ? *(const float4*)(Aptr + k0) : make_float4(0.f,0.f,0.f,0.f);
            rb0 = *(const float4*)(Bptr + (size_t)k0*ldb);
            rb1 = *(const float4*)(Bptr + (size_t)k0*ldb + 4);
        }
        #pragma unroll
        for (int k = 0; k < 16; k++) {
            float4 a = *(const float4*)&As[buf][k][ty<<2];
            float4 b = *(const float4*)&Bs[buf][k][tx<<2];
            acc[0][0] = fmaf(a.x, b.x, acc[0][0]);
            acc[0][1] = fmaf(a.x, b.y, acc[0][1]);
            acc[0][2] = fmaf(a.x, b.z, acc[0][2]);
            acc[0][3] = fmaf(a.x, b.w, acc[0][3]);
            acc[1][0] = fmaf(a.y, b.x, acc[1][0]);
            acc[1][1] = fmaf(a.y, b.y, acc[1][1]);
            acc[1][2] = fmaf(a.y, b.z, acc[1][2]);
            acc[1][3] = fmaf(a.y, b.w, acc[1][3]);
            acc[2][0] = fmaf(a.z, b.x, acc[2][0]);
            acc[2][1] = fmaf(a.z, b.y, acc[2][1]);
            acc[2][2] = fmaf(a.z, b.z, acc[2][2]);
            acc[2][3] = fmaf(a.z, b.w, acc[2][3]);
            acc[3][0] = fmaf(a.w, b.x, acc[3][0]);
            acc[3][1] = fmaf(a.w, b.y, acc[3][1]);
            acc[3][2] = fmaf(a.w, b.z, acc[3][2]);
            acc[3][3] = fmaf(a.w, b.w, acc[3][3]);
        }
        if (!more) break;
        buf ^= 1;
        As[buf][acol  ][arow] = ra.x; As[buf][acol+1][arow] = ra.y;
        As[buf][acol+2][arow] = ra.z; As[buf][acol+3][arow] = ra.w;
        *(float4*)&Bs[buf][brow][bcol]   = rb0;
        *(float4*)&Bs[buf][brow][bcol+4] = rb1;
        __syncthreads();
    }

    float4 bv = *(const float4*)(bias + n0 + (tx<<2));
    #pragma unroll
    for (int i = 0; i < 4; i++) {
        int m = m0 + (ty<<2) + i;
        if (m >= M) break;
        float4 v = make_float4(acc[i][0]+bv.x, acc[i][1]+bv.y,
                               acc[i][2]+bv.z, acc[i][3]+bv.w);
        if (flags & FLAG_RELU) {
            v.x = fmaxf(v.x,0.f); v.y = fmaxf(v.y,0.f);
            v.z = fmaxf(v.z,0.f); v.w = fmaxf(v.w,0.f);
        }
        float4* cp = (float4*)(C + (size_t)m*ldc + n0 + (tx<<2));
        if (flags & FLAG_ADD) {
            float4 o = *cp;
            v.x += o.x; v.y += o.y; v.z += o.z; v.w += o.w;
        }
        *cp = v;
    }
}

// ---------------- layernorm (one block per row) ----------------
__global__ void ln_kernel(const float* __restrict__ x, float* __restrict__ y,
                          const float* __restrict__ g, const float* __restrict__ b) {
    int row = blockIdx.x, t = threadIdx.x;     // 256 threads
    const float* xr = x + (size_t)row*DIMM;
    float v0 = xr[t], v1 = xr[t+256];
    float2 s = blockReduce2_256(v0+v1, v0*v0+v1*v1);
    float mean = s.x * (1.f/512.f);
    float inv  = rsqrtf(s.y*(1.f/512.f) - mean*mean + 1e-5f);
    y[(size_t)row*DIMM + t]       = (v0-mean)*inv*g[t]     + b[t];
    y[(size_t)row*DIMM + t + 256] = (v1-mean)*inv*g[t+256] + b[t+256];
}

// ---------------- QK^T scores + fused CPB bias ----------------
// 32 i-rows x 64 j-cols per CTA, 128 threads, 4x4/thread.
__global__ void __launch_bounds__(128) scores_kernel(const float* __restrict__ tab) {
    __shared__ __align__(16) float Qs[64][36];   // [d][i]
    __shared__ __align__(16) float Ks[64][68];   // [d][j]
    int h  = blockIdx.z;
    int i0 = blockIdx.y << 5, j0 = blockIdx.x << 6;
    int t  = threadIdx.x;

    {
        int r = t >> 2, c = (t & 3) << 4;
        const float* qp = g_qkv + (size_t)(i0+r)*QKV3 + h*HDIM + c;
        bool v = (i0 + r) < NTOK;
        #pragma unroll
        for (int q = 0; q < 4; q++) {
            float4 x = v ? *(const float4*)(qp + (q<<2)) : make_float4(0.f,0.f,0.f,0.f);
            int d = c + (q<<2);
            Qs[d  ][r] = x.x; Qs[d+1][r] = x.y;
            Qs[d+2][r] = x.z; Qs[d+3][r] = x.w;
        }
    }
    {
        int r = t >> 1, c = (t & 1) << 5;
        const float* kp = g_qkv + (size_t)(j0+r)*QKV3 + DIMM + h*HDIM + c;
        bool v = (j0 + r) < NTOK;
        #pragma unroll
        for (int q = 0; q < 8; q++) {
            float4 x = v ? *(const float4*)(kp + (q<<2)) : make_float4(0.f,0.f,0.f,0.f);
            int d = c + (q<<2);
            Ks[d  ][r] = x.x; Ks[d+1][r] = x.y;
            Ks[d+2][r] = x.z; Ks[d+3][r] = x.w;
        }
    }
    __syncthreads();

    int tx = t & 15, ty = t >> 4;
    float acc[4][4] = {};
    #pragma unroll 8
    for (int d = 0; d < 64; d++) {
        float4 a = *(const float4*)&Qs[d][ty<<2];
        float4 b = *(const float4*)&Ks[d][tx<<2];
        acc[0][0] = fmaf(a.x, b.x, acc[0][0]);
        acc[0][1] = fmaf(a.x, b.y, acc[0][1]);
        acc[0][2] = fmaf(a.x, b.z, acc[0][2]);
        acc[0][3] = fmaf(a.x, b.w, acc[0][3]);
        acc[1][0] = fmaf(a.y, b.x, acc[1][0]);
        acc[1][1] = fmaf(a.y, b.y, acc[1][1]);
        acc[1][2] = fmaf(a.y, b.z, acc[1][2]);
        acc[1][3] = fmaf(a.y, b.w, acc[1][3]);
        acc[2][0] = fmaf(a.z, b.x, acc[2][0]);
        acc[2][1] = fmaf(a.z, b.y, acc[2][1]);
        acc[2][2] = fmaf(a.z, b.z, acc[2][2]);
        acc[2][3] = fmaf(a.z, b.w, acc[2][3]);
        acc[3][0] = fmaf(a.w, b.x, acc[3][0]);
        acc[3][1] = fmaf(a.w, b.y, acc[3][1]);
        acc[3][2] = fmaf(a.w, b.z, acc[3][2]);
        acc[3][3] = fmaf(a.w, b.w, acc[3][3]);
    }

    #pragma unroll
    for (int qi = 0; qi < 4; qi++) {
        int i = i0 + (ty<<2) + qi;
        if (i >= NTOK) break;
        #pragma unroll
        for (int qj = 0; qj < 4; qj++) {
            int j = j0 + (tx<<2) + qj;
            if (j < NTOK) {
                size_t p = (size_t)i*NTOK + j;
                float pos = g_angpos[p];
                int   ip  = (int)pos;
                float f   = pos - (float)ip;
                const float* r0 = tab + (size_t)ip*8 + h;
                float bias = r0[0] + f*(r0[8] - r0[0]);
                g_attn[(size_t)h*NTOK*NTOK + p] = fmaf(0.125f, acc[qi][qj], bias);
            }
        }
    }
}

// ---------------- softmax over j, one block per (h,i) row ----------------
__global__ void softmax_kernel() {
    int row = blockIdx.x;                 // h*NTOK + i
    float* a = g_attn + (size_t)row*NTOK;
    int t = threadIdx.x;                  // 128 threads
    float vals[4];
    float mx = -1e30f;
    #pragma unroll
    for (int q = 0; q < 4; q++) {
        int j = t + q*128;
        vals[q] = (j < NTOK) ? a[j] : -1e30f;
        mx = fmaxf(mx, vals[q]);
    }
    #pragma unroll
    for (int o = 16; o > 0; o >>= 1)
        mx = fmaxf(mx, __shfl_xor_sync(0xffffffffu, mx, o));
    __shared__ float sm[4];
    if ((t & 31) == 0) sm[t >> 5] = mx;
    __syncthreads();
    mx = fmaxf(fmaxf(sm[0], sm[1]), fmaxf(sm[2], sm[3]));

    float s = 0.f;
    #pragma unroll
    for (int q = 0; q < 4; q++) {
        int j = t + q*128;
        if (j < NTOK) { vals[q] = __expf(vals[q] - mx); s += vals[q]; }
    }
    #pragma unroll
    for (int o = 16; o > 0; o >>= 1)
        s += __shfl_xor_sync(0xffffffffu, s, o);
    __shared__ float ss[4];
    if ((t & 31) == 0) ss[t >> 5] = s;
    __syncthreads();
    s = ss[0] + ss[1] + ss[2] + ss[3];
    float inv = 1.f / s;
    #pragma unroll
    for (int q = 0; q < 4; q++) {
        int j = t + q*128;
        if (j < NTOK) a[j] = vals[q] * inv;
    }
}

// ---------------- attn @ V  (per-head, 32 i-rows per block) ----------------
__global__ void __launch_bounds__(256) av_kernel() {
    __shared__ float sa[32][33];
    __shared__ __align__(16) float sv[32][68];
    int h  = blockIdx.y;
    int i0 = blockIdx.x << 5;
    int t  = threadIdx.x;
    int tx = t & 15, ty = t >> 4;         // tx -> d4, ty -> i pair
    int d4 = tx << 2;
    int ar = t >> 3, ac = (t & 7) << 2;
    int vr = t >> 3, vc = (t & 7) << 3;
    float acc[2][4] = {};
    for (int j0 = 0; j0 < NTOK; j0 += 32) {
        #pragma unroll
        for (int q = 0; q < 4; q++) {
            int i = i0 + ar, j = j0 + ac + q;
            sa[ar][ac+q] = (i < NTOK && j < NTOK)
                         ? g_attn[((size_t)h*NTOK + i)*NTOK + j] : 0.f;
        }
        {
            const float* vp = g_qkv + (size_t)(j0+vr)*QKV3 + 2*DIMM + h*HDIM + vc;
            bool vi = (j0 + vr < NTOK);
            float4 z = make_float4(0.f,0.f,0.f,0.f);
            float4 v0 = vi ? *(const float4*)vp       : z;
            float4 v1 = vi ? *(const float4*)(vp + 4) : z;
            *(float4*)&sv[vr][vc]   = v0;
            *(float4*)&sv[vr][vc+4] = v1;
        }
        __syncthreads();
        #pragma unroll
        for (int j = 0; j < 32; j++) {
            float4 vv = *(const float4*)&sv[j][d4];
            float a0 = sa[ty][j], a1 = sa[ty+16][j];
            acc[0][0] = fmaf(a0, vv.x, acc[0][0]);
            acc[0][1] = fmaf(a0, vv.y, acc[0][1]);
            acc[0][2] = fmaf(a0, vv.z, acc[0][2]);
            acc[0][3] = fmaf(a0, vv.w, acc[0][3]);
            acc[1][0] = fmaf(a1, vv.x, acc[1][0]);
            acc[1][1] = fmaf(a1, vv.y, acc[1][1]);
            acc[1][2] = fmaf(a1, vv.z, acc[1][2]);
            acc[1][3] = fmaf(a1, vv.w, acc[1][3]);
        }
        __syncthreads();
    }
    #pragma unroll
    for (int q = 0; q < 2; q++) {
        int i = i0 + ty + (q<<4);
        if (i < NTOK)
            *(float4*)(g_ao + (size_t)i*DIMM + h*HDIM + d4) =
                make_float4(acc[q][0], acc[q][1], acc[q][2], acc[q][3]);
    }
}

// ---------------- final: LN(row 0) -> fc2 -> out[2] ----------------
__global__ void final_kernel(const float* __restrict__ g, const float* __restrict__ b,
                             const float* __restrict__ w, const float* __restrict__ bias,
                             float* __restrict__ out) {
    int t = threadIdx.x;                  // 256 threads
    float v0 = g_h[t], v1 = g_h[t+256];
    float2 s = blockReduce2_256(v0+v1, v0*v0+v1*v1);
    float mean = s.x * (1.f/512.f);
    float inv  = rsqrtf(s.y*(1.f/512.f) - mean*mean + 1e-5f);
    float l0 = (v0-mean)*inv*g[t]     + b[t];
    float l1 = (v1-mean)*inv*g[t+256] + b[t+256];
    float p0 = l0*w[t*2]   + l1*w[(t+256)*2];
    float p1 = l0*w[t*2+1] + l1*w[(t+256)*2+1];
    float2 sp = blockReduce2_256(p0, p1);
    if (t == 0) { out[0] = sp.x + bias[0]; out[1] = sp.y + bias[1]; }
}

// ---------------- launch ----------------
extern "C" void kernel_launch(void* const* d_in, const int* in_sizes, int n_in,
                              void* d_out, int out_size) {
    const float* h_in   = (const float*)d_in[0];
    const float* coords = (const float*)d_in[1];
    const float* fc1_w  = (const float*)d_in[2];
    const float* fc1_b  = (const float*)d_in[3];
    const float* cls    = (const float*)d_in[4];
    const float* norm_g = (const float*)d_in[25];
    const float* norm_b = (const float*)d_in[26];
    const float* fc2_w  = (const float*)d_in[27];
    const float* fc2_b  = (const float*)d_in[28];

    float *p_h, *p_ln, *p_qkv, *p_ao, *p_tab[2];
    cudaGetSymbolAddress((void**)&p_h,      g_h);
    cudaGetSymbolAddress((void**)&p_ln,     g_ln);
    cudaGetSymbolAddress((void**)&p_qkv,    g_qkv);
    cudaGetSymbolAddress((void**)&p_ao,     g_ao);
    cudaGetSymbolAddress((void**)&p_tab[0], g_table0);
    cudaGetSymbolAddress((void**)&p_tab[1], g_table1);

    // one-time side stream + events (created OUTSIDE capture: first call is
    // the eager correctness run)
    static cudaStream_t s_side = 0;
    static cudaEvent_t evFork, evTab, evLn[2], evV[2];
    static int inited = 0;
    if (!inited) {
        cudaStreamCreateWithFlags(&s_side, cudaStreamNonBlocking);
        cudaEventCreateWithFlags(&evFork,  cudaEventDisableTiming);
        cudaEventCreateWithFlags(&evTab,   cudaEventDisableTiming);
        cudaEventCreateWithFlags(&evLn[0], cudaEventDisableTiming);
        cudaEventCreateWithFlags(&evLn[1], cudaEventDisableTiming);
        cudaEventCreateWithFlags(&evV[0],  cudaEventDisableTiming);
        cudaEventCreateWithFlags(&evV[1],  cudaEventDisableTiming);
        inited = 1;
    }

    // main chain on the default stream; side work forked via events
    setup_kernel<<<4, 256>>>(cls, coords);
    cudaEventRecord(evFork, 0);
    cudaStreamWaitEvent(s_side, evFork, 0);

    // side stream: angle positions + BOTH layers' CPB tables
    angpos_kernel<<<(NPAIR + 255)/256, 256, 0, s_side>>>();
    for (int L = 0; L < 2; L++) {
        const float* w1 = (const float*)d_in[5 + L*10 + 2];
        const float* b1 = (const float*)d_in[5 + L*10 + 3];
        const float* w2 = (const float*)d_in[5 + L*10 + 4];
        const float* b2 = (const float*)d_in[5 + L*10 + 5];
        cpb_table_kernel<<<(TABN + 3 + 31)/32, 256, 0, s_side>>>(w1, b1, w2, b2, p_tab[L]);
    }
    cudaEventRecord(evTab, s_side);

    // fc1 + relu into rows 1..400 of residual stream (overlaps side work)
    gemm_kernel<<<dim3(DIMM/64, (NPT+31)/32), 128>>>(
        h_in, 1024, fc1_w, DIMM, fc1_b, p_h + DIMM, DIMM, NPT, DIMM, 1024, FLAG_RELU);

    for (int L = 0; L < 2; L++) {
        const float* lp[10];
        for (int q = 0; q < 10; q++) lp[q] = (const float*)d_in[5 + L*10 + q];
        const float* ln_g   = lp[0]; const float* ln_b   = lp[1];
        const float* qkv_w  = lp[6]; const float* qkv_b  = lp[7];
        const float* proj_w = lp[8]; const float* proj_b = lp[9];

        ln_kernel<<<NTOK, 256>>>(p_h, p_ln, ln_g, ln_b);
        cudaEventRecord(evLn[L], 0);

        // V-part GEMM on the side stream (overlaps QK gemm + scores + softmax)
        cudaStreamWaitEvent(s_side, evLn[L], 0);
        gemm_kernel<<<dim3(DIMM/64, (NTOK+31)/32), 128, 0, s_side>>>(
            p_ln, DIMM, qkv_w + 2*DIMM, QKV3, qkv_b + 2*DIMM,
            p_qkv + 2*DIMM, QKV3, NTOK, DIMM, DIMM, 0);
        cudaEventRecord(evV[L], s_side);

        // QK-part GEMM on the main stream
        gemm_kernel<<<dim3(2*DIMM/64, (NTOK+31)/32), 128>>>(
            p_ln, DIMM, qkv_w, QKV3, qkv_b, p_qkv, QKV3, NTOK, 2*DIMM, DIMM, 0);

        if (L == 0) cudaStreamWaitEvent(0, evTab, 0);  // tables ready before scores
        scores_kernel<<<dim3(7, 13, NHEAD), 128>>>(p_tab[L]);
        softmax_kernel<<<NHEAD*NTOK, 128>>>();

        cudaStreamWaitEvent(0, evV[L], 0);             // V ready before av
        av_kernel<<<dim3(13, NHEAD), 256>>>();
        gemm_kernel<<<dim3(DIMM/64, (NTOK+31)/32), 128>>>(
            p_ao, DIMM, proj_w, DIMM, proj_b, p_h, DIMM, NTOK, DIMM, DIMM, FLAG_ADD);
    }

    final_kernel<<<1, 256>>>(norm_g, norm_b, fc2_w, fc2_b, (float*)d_out);
}

// round 8
// speedup vs baseline: 1.3687x; 1.3687x over previous
#include <cuda_runtime.h>
#include <math.h>

#define NTOK 401
#define NPT  400
#define DIMM 512
#define NHEAD 8
#define HDIM 64
#define QKV3 1536
#define CPBH 512
#define NPAIR (NTOK*NTOK)
#define TABN 4096
#define PI_F 3.14159265358979323846f
#define FLAG_RELU 1
#define FLAG_ADD  2

// ---------------- scratch (alloc-free, __device__ globals) ----------------
__device__ float  g_h[NTOK*DIMM];          // residual stream
__device__ float  g_ln[NTOK*DIMM];         // layernorm output
__device__ float  g_qkv[NTOK*QKV3];        // fused qkv
__device__ float  g_attn[NHEAD*NTOK*NTOK]; // attention logits (5.1 MB)
__device__ float  g_ao[NTOK*DIMM];         // attention output (pre-proj)
__device__ float  g_angpos[NPAIR];         // table position per pair (both layers)
__device__ float  g_coords[NTOK*2];
__device__ float  g_table0[(TABN+4)*8];    // layer-1 bias table
__device__ float  g_table1[(TABN+4)*8];    // layer-2 bias table

// ---------------- small helpers ----------------
__device__ __forceinline__ float2 blockReduce2_256(float a, float b) {
    __shared__ float sa[8], sb[8];
    __syncthreads();
    #pragma unroll
    for (int o = 16; o > 0; o >>= 1) {
        a += __shfl_xor_sync(0xffffffffu, a, o);
        b += __shfl_xor_sync(0xffffffffu, b, o);
    }
    int w = threadIdx.x >> 5;
    if ((threadIdx.x & 31) == 0) { sa[w] = a; sb[w] = b; }
    __syncthreads();
    a = sa[0]+sa[1]+sa[2]+sa[3]+sa[4]+sa[5]+sa[6]+sa[7];
    b = sb[0]+sb[1]+sb[2]+sb[3]+sb[4]+sb[5]+sb[6]+sb[7];
    return make_float2(a, b);
}

// ---------------- setup: CLS row + coords (CLS coord = 0) ----------------
__global__ void setup_kernel(const float* __restrict__ cls,
                             const float* __restrict__ coords) {
    int t = blockIdx.x*blockDim.x + threadIdx.x;
    if (t < DIMM)  g_h[t] = cls[t];
    if (t < 2)     g_coords[t] = 0.f;
    if (t < NPT*2) g_coords[2+t] = coords[t];
}

// ---------------- per-pair angle table position ----------------
__global__ void angpos_kernel() {
    int p = blockIdx.x*blockDim.x + threadIdx.x;
    if (p >= NPAIR) return;
    int i = p / NTOK, j = p - i*NTOK;
    float pos;
    if (i == j) {
        pos = (float)(TABN + 1);           // diag: dir = (0,0) special row
    } else {
        float dx = g_coords[2*i]   - g_coords[2*j];
        float dy = g_coords[2*i+1] - g_coords[2*j+1];
        float th = atan2f(dy, dx);
        pos = (th + PI_F) * ((float)TABN / (2.0f*PI_F));
        pos = fminf(fmaxf(pos, 0.f), (float)TABN);
    }
    g_angpos[p] = pos;
}

// ---------------- build CPB bias tables (both layers, grid.y selects) ----
// 256 threads = 8 warps (channel groups of 64) x 32 lanes (entries).
// All lanes in a warp read the SAME channel -> broadcast LDS, conflict-free.
__global__ void __launch_bounds__(256) cpb_table_kernel(
        const float* __restrict__ w1a, const float* __restrict__ b1a,
        const float* __restrict__ w2a, const float* __restrict__ b2a,
        float* __restrict__ outa,
        const float* __restrict__ w1b, const float* __restrict__ b1b,
        const float* __restrict__ w2b, const float* __restrict__ b2b,
        float* __restrict__ outb) {
    const float* w1 = blockIdx.y ? w1b : w1a;
    const float* b1 = blockIdx.y ? b1b : b1a;
    const float* w2 = blockIdx.y ? w2b : w2a;
    const float* b2 = blockIdx.y ? b2b : b2a;
    float*      out = blockIdx.y ? outb : outa;

    __shared__ float swx[CPBH], swy[CPBH], sbb[CPBH];
    __shared__ __align__(16) float sw2[CPBH*8];
    __shared__ float sred[8][32][9];       // padded: 9 coprime 32 -> no conflicts
    int t = threadIdx.x;
    for (int c = t; c < CPBH; c += 256) {
        swx[c] = w1[c]; swy[c] = w1[CPBH + c]; sbb[c] = b1[c];
    }
    for (int c = t; c < CPBH*2; c += 256)
        *(float4*)(sw2 + c*4) = *(const float4*)(w2 + c*4);
    __syncthreads();

    int e = t & 31;                     // entry (lane)
    int w = t >> 5;                     // warp = channel group
    int idx = blockIdx.x*32 + e;
    float ux = 0.f, uy = 0.f;
    if (idx <= TABN) {
        float th = -PI_F + (2.0f*PI_F) * ((float)idx / (float)TABN);
        sincosf(th, &uy, &ux);
    }
    float acc[8] = {0.f,0.f,0.f,0.f,0.f,0.f,0.f,0.f};
    int c0 = w << 6;
    #pragma unroll 8
    for (int cc = 0; cc < 64; cc++) {
        int c = c0 + cc;
        float hv = fmaf(ux, swx[c], fmaf(uy, swy[c], sbb[c]));  // broadcast
        hv = fmaxf(hv, 0.f);
        float4 wa = *(const float4*)(sw2 + (c<<3));             // broadcast
        float4 wb = *(const float4*)(sw2 + (c<<3) + 4);         // broadcast
        acc[0] = fmaf(hv, wa.x, acc[0]);
        acc[1] = fmaf(hv, wa.y, acc[1]);
        acc[2] = fmaf(hv, wa.z, acc[2]);
        acc[3] = fmaf(hv, wa.w, acc[3]);
        acc[4] = fmaf(hv, wb.x, acc[4]);
        acc[5] = fmaf(hv, wb.y, acc[5]);
        acc[6] = fmaf(hv, wb.z, acc[6]);
        acc[7] = fmaf(hv, wb.w, acc[7]);
    }
    #pragma unroll
    for (int k = 0; k < 8; k++) sred[w][e][k] = acc[k];
    __syncthreads();

    int re = t >> 3, rk = t & 7;
    float s = 0.f;
    #pragma unroll
    for (int ww = 0; ww < 8; ww++) s += sred[ww][re][rk];
    int ridx = blockIdx.x*32 + re;
    if (ridx <= TABN + 2) {
        float v = (ridx == TABN + 2) ? 0.f : s + b2[rk];
        out[(size_t)ridx*8 + rk] = v;
    }
}

// ---------------- 32x64-tile fp32 GEMM, 128 threads, 4x4/thread ----------
// C = A[M,K] @ B[K,N] (+bias, opt relu / add). K%16==0, N%64==0.
__global__ void __launch_bounds__(128) gemm_kernel(
        const float* __restrict__ A, const float* __restrict__ B,
        const float* __restrict__ bias, float* __restrict__ C,
        int M, int N, int K, int flags) {
    __shared__ __align__(16) float As[2][16][36];
    __shared__ __align__(16) float Bs[2][16][68];
    int t  = threadIdx.x;
    int m0 = blockIdx.y << 5, n0 = blockIdx.x << 6;
    int arow = t >> 2, acol = (t & 3) << 2;
    int brow = t >> 3, bcol = (t & 7) << 3;
    int tx = t & 15, ty = t >> 4;
    float acc[4][4] = {};

    bool aval = (m0 + arow) < M;
    const float* Aptr = A + (size_t)(m0 + arow)*K + acol;
    const float* Bptr = B + (size_t)brow*N + n0 + bcol;

    float4 ra  = aval ? *(const float4*)Aptr : make_float4(0.f,0.f,0.f,0.f);
    float4 rb0 = *(const float4*)Bptr;
    float4 rb1 = *(const float4*)(Bptr + 4);
    int buf = 0;
    As[0][acol  ][arow] = ra.x; As[0][acol+1][arow] = ra.y;
    As[0][acol+2][arow] = ra.z; As[0][acol+3][arow] = ra.w;
    *(float4*)&Bs[0][brow][bcol]   = rb0;
    *(float4*)&Bs[0][brow][bcol+4] = rb1;
    __syncthreads();

    for (int k0 = 16; ; k0 += 16) {
        bool more = (k0 < K);
        if (more) {
            ra  = aval ? *(const float4*)(Aptr + k0) : make_float4(0.f,0.f,0.f,0.f);
            rb0 = *(const float4*)(Bptr + (size_t)k0*N);
            rb1 = *(const float4*)(Bptr + (size_t)k0*N + 4);
        }
        #pragma unroll
        for (int k = 0; k < 16; k++) {
            float4 a = *(const float4*)&As[buf][k][ty<<2];
            float4 b = *(const float4*)&Bs[buf][k][tx<<2];
            acc[0][0] = fmaf(a.x, b.x, acc[0][0]);
            acc[0][1] = fmaf(a.x, b.y, acc[0][1]);
            acc[0][2] = fmaf(a.x, b.z, acc[0][2]);
            acc[0][3] = fmaf(a.x, b.w, acc[0][3]);
            acc[1][0] = fmaf(a.y, b.x, acc[1][0]);
            acc[1][1] = fmaf(a.y, b.y, acc[1][1]);
            acc[1][2] = fmaf(a.y, b.z, acc[1][2]);
            acc[1][3] = fmaf(a.y, b.w, acc[1][3]);
            acc[2][0] = fmaf(a.z, b.x, acc[2][0]);
            acc[2][1] = fmaf(a.z, b.y, acc[2][1]);
            acc[2][2] = fmaf(a.z, b.z, acc[2][2]);
            acc[2][3] = fmaf(a.z, b.w, acc[2][3]);
            acc[3][0] = fmaf(a.w, b.x, acc[3][0]);
            acc[3][1] = fmaf(a.w, b.y, acc[3][1]);
            acc[3][2] = fmaf(a.w, b.z, acc[3][2]);
            acc[3][3] = fmaf(a.w, b.w, acc[3][3]);
        }
        if (!more) break;
        buf ^= 1;
        As[buf][acol  ][arow] = ra.x; As[buf][acol+1][arow] = ra.y;
        As[buf][acol+2][arow] = ra.z; As[buf][acol+3][arow] = ra.w;
        *(float4*)&Bs[buf][brow][bcol]   = rb0;
        *(float4*)&Bs[buf][brow][bcol+4] = rb1;
        __syncthreads();
    }

    float4 bv = *(const float4*)(bias + n0 + (tx<<2));
    #pragma unroll
    for (int i = 0; i < 4; i++) {
        int m = m0 + (ty<<2) + i;
        if (m >= M) break;
        float4 v = make_float4(acc[i][0]+bv.x, acc[i][1]+bv.y,
                               acc[i][2]+bv.z, acc[i][3]+bv.w);
        if (flags & FLAG_RELU) {
            v.x = fmaxf(v.x,0.f); v.y = fmaxf(v.y,0.f);
            v.z = fmaxf(v.z,0.f); v.w = fmaxf(v.w,0.f);
        }
        float4* cp = (float4*)(C + (size_t)m*N + n0 + (tx<<2));
        if (flags & FLAG_ADD) {
            float4 o = *cp;
            v.x += o.x; v.y += o.y; v.z += o.z; v.w += o.w;
        }
        *cp = v;
    }
}

// ---------------- layernorm (one block per row) ----------------
__global__ void ln_kernel(const float* __restrict__ x, float* __restrict__ y,
                          const float* __restrict__ g, const float* __restrict__ b) {
    int row = blockIdx.x, t = threadIdx.x;     // 256 threads
    const float* xr = x + (size_t)row*DIMM;
    float v0 = xr[t], v1 = xr[t+256];
    float2 s = blockReduce2_256(v0+v1, v0*v0+v1*v1);
    float mean = s.x * (1.f/512.f);
    float inv  = rsqrtf(s.y*(1.f/512.f) - mean*mean + 1e-5f);
    y[(size_t)row*DIMM + t]       = (v0-mean)*inv*g[t]     + b[t];
    y[(size_t)row*DIMM + t + 256] = (v1-mean)*inv*g[t+256] + b[t+256];
}

// ---------------- QK^T scores + fused CPB bias ----------------
// 32 i-rows x 64 j-cols per CTA, 128 threads, 4x4/thread.
__global__ void __launch_bounds__(128) scores_kernel(const float* __restrict__ tab) {
    __shared__ __align__(16) float Qs[64][36];   // [d][i]
    __shared__ __align__(16) float Ks[64][68];   // [d][j]
    int h  = blockIdx.z;
    int i0 = blockIdx.y << 5, j0 = blockIdx.x << 6;
    int t  = threadIdx.x;

    {
        int r = t >> 2, c = (t & 3) << 4;
        const float* qp = g_qkv + (size_t)(i0+r)*QKV3 + h*HDIM + c;
        bool v = (i0 + r) < NTOK;
        #pragma unroll
        for (int q = 0; q < 4; q++) {
            float4 x = v ? *(const float4*)(qp + (q<<2)) : make_float4(0.f,0.f,0.f,0.f);
            int d = c + (q<<2);
            Qs[d  ][r] = x.x; Qs[d+1][r] = x.y;
            Qs[d+2][r] = x.z; Qs[d+3][r] = x.w;
        }
    }
    {
        int r = t >> 1, c = (t & 1) << 5;
        const float* kp = g_qkv + (size_t)(j0+r)*QKV3 + DIMM + h*HDIM + c;
        bool v = (j0 + r) < NTOK;
        #pragma unroll
        for (int q = 0; q < 8; q++) {
            float4 x = v ? *(const float4*)(kp + (q<<2)) : make_float4(0.f,0.f,0.f,0.f);
            int d = c + (q<<2);
            Ks[d  ][r] = x.x; Ks[d+1][r] = x.y;
            Ks[d+2][r] = x.z; Ks[d+3][r] = x.w;
        }
    }
    __syncthreads();

    int tx = t & 15, ty = t >> 4;
    float acc[4][4] = {};
    #pragma unroll 8
    for (int d = 0; d < 64; d++) {
        float4 a = *(const float4*)&Qs[d][ty<<2];
        float4 b = *(const float4*)&Ks[d][tx<<2];
        acc[0][0] = fmaf(a.x, b.x, acc[0][0]);
        acc[0][1] = fmaf(a.x, b.y, acc[0][1]);
        acc[0][2] = fmaf(a.x, b.z, acc[0][2]);
        acc[0][3] = fmaf(a.x, b.w, acc[0][3]);
        acc[1][0] = fmaf(a.y, b.x, acc[1][0]);
        acc[1][1] = fmaf(a.y, b.y, acc[1][1]);
        acc[1][2] = fmaf(a.y, b.z, acc[1][2]);
        acc[1][3] = fmaf(a.y, b.w, acc[1][3]);
        acc[2][0] = fmaf(a.z, b.x, acc[2][0]);
        acc[2][1] = fmaf(a.z, b.y, acc[2][1]);
        acc[2][2] = fmaf(a.z, b.z, acc[2][2]);
        acc[2][3] = fmaf(a.z, b.w, acc[2][3]);
        acc[3][0] = fmaf(a.w, b.x, acc[3][0]);
        acc[3][1] = fmaf(a.w, b.y, acc[3][1]);
        acc[3][2] = fmaf(a.w, b.z, acc[3][2]);
        acc[3][3] = fmaf(a.w, b.w, acc[3][3]);
    }

    #pragma unroll
    for (int qi = 0; qi < 4; qi++) {
        int i = i0 + (ty<<2) + qi;
        if (i >= NTOK) break;
        #pragma unroll
        for (int qj = 0; qj < 4; qj++) {
            int j = j0 + (tx<<2) + qj;
            if (j < NTOK) {
                size_t p = (size_t)i*NTOK + j;
                float pos = g_angpos[p];
                int   ip  = (int)pos;
                float f   = pos - (float)ip;
                const float* r0 = tab + (size_t)ip*8 + h;
                float bias = r0[0] + f*(r0[8] - r0[0]);
                g_attn[(size_t)h*NTOK*NTOK + p] = fmaf(0.125f, acc[qi][qj], bias);
            }
        }
    }
}

// ---------------- fused softmax + attn@V (per-head, 32 i-rows) ------------
// Pass 1: per-row max and sum(exp) over logits (8 threads/row).
// Pass 2: AV with exp applied at the sa-tile load; 1/sum applied at the end.
__global__ void __launch_bounds__(256) softav_kernel() {
    __shared__ float sa[32][33];
    __shared__ __align__(16) float sv[32][68];
    __shared__ float smx[32], sinv[32];
    int h  = blockIdx.y;
    int i0 = blockIdx.x << 5;
    int t  = threadIdx.x;

    // ---- pass 1: row stats (rows clamped so shuffles stay convergent) ----
    {
        int row = t >> 3, k8 = t & 7;
        int gi  = i0 + row;
        int cgi = gi < NTOK ? gi : NTOK - 1;
        const float* arow = g_attn + ((size_t)h*NTOK + cgi)*NTOK;
        float m = -1e30f;
        for (int j = k8; j < NTOK; j += 8) m = fmaxf(m, arow[j]);
        #pragma unroll
        for (int o = 1; o < 8; o <<= 1)
            m = fmaxf(m, __shfl_xor_sync(0xffffffffu, m, o));
        float s = 0.f;
        for (int j = k8; j < NTOK; j += 8) s += __expf(arow[j] - m);
        #pragma unroll
        for (int o = 1; o < 8; o <<= 1)
            s += __shfl_xor_sync(0xffffffffu, s, o);
        if (k8 == 0) { smx[row] = m; sinv[row] = 1.f / s; }
    }
    __syncthreads();

    // ---- pass 2: AV ----
    int tx = t & 15, ty = t >> 4;
    int d4 = tx << 2;
    int ar = t >> 3, ac = (t & 7) << 2;
    int vr = t >> 3, vc = (t & 7) << 3;
    float mrow = smx[ar];
    float acc[2][4] = {};
    for (int j0 = 0; j0 < NTOK; j0 += 32) {
        #pragma unroll
        for (int q = 0; q < 4; q++) {
            int i = i0 + ar, j = j0 + ac + q;
            float e = 0.f;
            if (i < NTOK && j < NTOK)
                e = __expf(g_attn[((size_t)h*NTOK + i)*NTOK + j] - mrow);
            sa[ar][ac+q] = e;
        }
        {
            const float* vp = g_qkv + (size_t)(j0+vr)*QKV3 + 2*DIMM + h*HDIM + vc;
            bool vi = (j0 + vr < NTOK);
            float4 z = make_float4(0.f,0.f,0.f,0.f);
            float4 v0 = vi ? *(const float4*)vp       : z;
            float4 v1 = vi ? *(const float4*)(vp + 4) : z;
            *(float4*)&sv[vr][vc]   = v0;
            *(float4*)&sv[vr][vc+4] = v1;
        }
        __syncthreads();
        #pragma unroll
        for (int j = 0; j < 32; j++) {
            float4 vv = *(const float4*)&sv[j][d4];
            float a0 = sa[ty][j], a1 = sa[ty+16][j];
            acc[0][0] = fmaf(a0, vv.x, acc[0][0]);
            acc[0][1] = fmaf(a0, vv.y, acc[0][1]);
            acc[0][2] = fmaf(a0, vv.z, acc[0][2]);
            acc[0][3] = fmaf(a0, vv.w, acc[0][3]);
            acc[1][0] = fmaf(a1, vv.x, acc[1][0]);
            acc[1][1] = fmaf(a1, vv.y, acc[1][1]);
            acc[1][2] = fmaf(a1, vv.z, acc[1][2]);
            acc[1][3] = fmaf(a1, vv.w, acc[1][3]);
        }
        __syncthreads();
    }
    #pragma unroll
    for (int q = 0; q < 2; q++) {
        int i = i0 + ty + (q<<4);
        if (i < NTOK) {
            float inv = sinv[ty + (q<<4)];
            *(float4*)(g_ao + (size_t)i*DIMM + h*HDIM + d4) =
                make_float4(acc[q][0]*inv, acc[q][1]*inv,
                            acc[q][2]*inv, acc[q][3]*inv);
        }
    }
}

// ---------------- final: LN(row 0) -> fc2 -> out[2] ----------------
__global__ void final_kernel(const float* __restrict__ g, const float* __restrict__ b,
                             const float* __restrict__ w, const float* __restrict__ bias,
                             float* __restrict__ out) {
    int t = threadIdx.x;                  // 256 threads
    float v0 = g_h[t], v1 = g_h[t+256];
    float2 s = blockReduce2_256(v0+v1, v0*v0+v1*v1);
    float mean = s.x * (1.f/512.f);
    float inv  = rsqrtf(s.y*(1.f/512.f) - mean*mean + 1e-5f);
    float l0 = (v0-mean)*inv*g[t]     + b[t];
    float l1 = (v1-mean)*inv*g[t+256] + b[t+256];
    float p0 = l0*w[t*2]   + l1*w[(t+256)*2];
    float p1 = l0*w[t*2+1] + l1*w[(t+256)*2+1];
    float2 sp = blockReduce2_256(p0, p1);
    if (t == 0) { out[0] = sp.x + bias[0]; out[1] = sp.y + bias[1]; }
}

// ---------------- launch ----------------
extern "C" void kernel_launch(void* const* d_in, const int* in_sizes, int n_in,
                              void* d_out, int out_size) {
    const float* h_in   = (const float*)d_in[0];
    const float* coords = (const float*)d_in[1];
    const float* fc1_w  = (const float*)d_in[2];
    const float* fc1_b  = (const float*)d_in[3];
    const float* cls    = (const float*)d_in[4];
    const float* norm_g = (const float*)d_in[25];
    const float* norm_b = (const float*)d_in[26];
    const float* fc2_w  = (const float*)d_in[27];
    const float* fc2_b  = (const float*)d_in[28];

    float *p_h, *p_ln, *p_qkv, *p_ao, *p_tab[2];
    cudaGetSymbolAddress((void**)&p_h,      g_h);
    cudaGetSymbolAddress((void**)&p_ln,     g_ln);
    cudaGetSymbolAddress((void**)&p_qkv,    g_qkv);
    cudaGetSymbolAddress((void**)&p_ao,     g_ao);
    cudaGetSymbolAddress((void**)&p_tab[0], g_table0);
    cudaGetSymbolAddress((void**)&p_tab[1], g_table1);

    setup_kernel<<<4, 256>>>(cls, coords);
    angpos_kernel<<<(NPAIR + 255)/256, 256>>>();
    // both layers' CPB tables in one launch
    cpb_table_kernel<<<dim3((TABN + 3 + 31)/32, 2), 256>>>(
        (const float*)d_in[7],  (const float*)d_in[8],
        (const float*)d_in[9],  (const float*)d_in[10], p_tab[0],
        (const float*)d_in[17], (const float*)d_in[18],
        (const float*)d_in[19], (const float*)d_in[20], p_tab[1]);
    // fc1 + relu into rows 1..400 of residual stream
    gemm_kernel<<<dim3(DIMM/64, (NPT+31)/32), 128>>>(
        h_in, fc1_w, fc1_b, p_h + DIMM, NPT, DIMM, 1024, FLAG_RELU);

    for (int L = 0; L < 2; L++) {
        const float* lp[10];
        for (int q = 0; q < 10; q++) lp[q] = (const float*)d_in[5 + L*10 + q];
        const float* ln_g   = lp[0]; const float* ln_b   = lp[1];
        const float* qkv_w  = lp[6]; const float* qkv_b  = lp[7];
        const float* proj_w = lp[8]; const float* proj_b = lp[9];

        ln_kernel<<<NTOK, 256>>>(p_h, p_ln, ln_g, ln_b);
        gemm_kernel<<<dim3(QKV3/64, (NTOK+31)/32), 128>>>(
            p_ln, qkv_w, qkv_b, p_qkv, NTOK, QKV3, DIMM, 0);
        scores_kernel<<<dim3(7, 13, NHEAD), 128>>>(p_tab[L]);
        softav_kernel<<<dim3(13, NHEAD), 256>>>();
        gemm_kernel<<<dim3(DIMM/64, (NTOK+31)/32), 128>>>(
            p_ao, proj_w, proj_b, p_h, NTOK, DIMM, DIMM, FLAG_ADD);
    }

    final_kernel<<<1, 256>>>(norm_g, norm_b, fc2_w, fc2_b, (float*)d_out);
}

// round 9
// speedup vs baseline: 1.3987x; 1.0219x over previous
#include <cuda_runtime.h>
#include <math.h>

#define NTOK 401
#define NPT  400
#define DIMM 512
#define NHEAD 8
#define HDIM 64
#define QKV3 1536
#define CPBH 512
#define NPAIR (NTOK*NTOK)
#define TABN 4096
#define PI_F 3.14159265358979323846f
#define FLAG_RELU 1
#define FLAG_ADD  2

// ---------------- scratch (alloc-free, __device__ globals) ----------------
__device__ float  g_h[NTOK*DIMM];          // residual stream
__device__ float  g_ln[NTOK*DIMM];         // layernorm output
__device__ float  g_qkv[NTOK*QKV3];        // fused qkv
__device__ float  g_attn[NHEAD*NTOK*NTOK]; // attention logits (5.1 MB)
__device__ float  g_ao[NTOK*DIMM];         // attention output (pre-proj)
__device__ float  g_angpos[NPAIR];         // table position per pair (both layers)
__device__ float  g_coords[NTOK*2];
__device__ float  g_table0[(TABN+4)*8];    // layer-1 bias table
__device__ float  g_table1[(TABN+4)*8];    // layer-2 bias table

// ---------------- small helpers ----------------
__device__ __forceinline__ float2 blockReduce2_256(float a, float b) {
    __shared__ float sa[8], sb[8];
    __syncthreads();
    #pragma unroll
    for (int o = 16; o > 0; o >>= 1) {
        a += __shfl_xor_sync(0xffffffffu, a, o);
        b += __shfl_xor_sync(0xffffffffu, b, o);
    }
    int w = threadIdx.x >> 5;
    if ((threadIdx.x & 31) == 0) { sa[w] = a; sb[w] = b; }
    __syncthreads();
    a = sa[0]+sa[1]+sa[2]+sa[3]+sa[4]+sa[5]+sa[6]+sa[7];
    b = sb[0]+sb[1]+sb[2]+sb[3]+sb[4]+sb[5]+sb[6]+sb[7];
    return make_float2(a, b);
}

// ---------------- setup: CLS row + coords (CLS coord = 0) ----------------
__global__ void setup_kernel(const float* __restrict__ cls,
                             const float* __restrict__ coords) {
    int t = blockIdx.x*blockDim.x + threadIdx.x;
    if (t < DIMM)  g_h[t] = cls[t];
    if (t < 2)     g_coords[t] = 0.f;
    if (t < NPT*2) g_coords[2+t] = coords[t];
}

// ---------------- per-pair angle table position ----------------
__global__ void angpos_kernel() {
    int p = blockIdx.x*blockDim.x + threadIdx.x;
    if (p >= NPAIR) return;
    int i = p / NTOK, j = p - i*NTOK;
    float pos;
    if (i == j) {
        pos = (float)(TABN + 1);           // diag: dir = (0,0) special row
    } else {
        float dx = g_coords[2*i]   - g_coords[2*j];
        float dy = g_coords[2*i+1] - g_coords[2*j+1];
        float th = atan2f(dy, dx);
        pos = (th + PI_F) * ((float)TABN / (2.0f*PI_F));
        pos = fminf(fmaxf(pos, 0.f), (float)TABN);
    }
    g_angpos[p] = pos;
}

// ---------------- build CPB bias tables (both layers, grid.y selects) ----
__global__ void __launch_bounds__(256) cpb_table_kernel(
        const float* __restrict__ w1a, const float* __restrict__ b1a,
        const float* __restrict__ w2a, const float* __restrict__ b2a,
        float* __restrict__ outa,
        const float* __restrict__ w1b, const float* __restrict__ b1b,
        const float* __restrict__ w2b, const float* __restrict__ b2b,
        float* __restrict__ outb) {
    const float* w1 = blockIdx.y ? w1b : w1a;
    const float* b1 = blockIdx.y ? b1b : b1a;
    const float* w2 = blockIdx.y ? w2b : w2a;
    const float* b2 = blockIdx.y ? b2b : b2a;
    float*      out = blockIdx.y ? outb : outa;

    __shared__ float swx[CPBH], swy[CPBH], sbb[CPBH];
    __shared__ __align__(16) float sw2[CPBH*8];
    __shared__ float sred[8][32][9];
    int t = threadIdx.x;
    for (int c = t; c < CPBH; c += 256) {
        swx[c] = w1[c]; swy[c] = w1[CPBH + c]; sbb[c] = b1[c];
    }
    for (int c = t; c < CPBH*2; c += 256)
        *(float4*)(sw2 + c*4) = *(const float4*)(w2 + c*4);
    __syncthreads();

    int e = t & 31;
    int w = t >> 5;
    int idx = blockIdx.x*32 + e;
    float ux = 0.f, uy = 0.f;
    if (idx <= TABN) {
        float th = -PI_F + (2.0f*PI_F) * ((float)idx / (float)TABN);
        sincosf(th, &uy, &ux);
    }
    float acc[8] = {0.f,0.f,0.f,0.f,0.f,0.f,0.f,0.f};
    int c0 = w << 6;
    #pragma unroll 8
    for (int cc = 0; cc < 64; cc++) {
        int c = c0 + cc;
        float hv = fmaf(ux, swx[c], fmaf(uy, swy[c], sbb[c]));
        hv = fmaxf(hv, 0.f);
        float4 wa = *(const float4*)(sw2 + (c<<3));
        float4 wb = *(const float4*)(sw2 + (c<<3) + 4);
        acc[0] = fmaf(hv, wa.x, acc[0]);
        acc[1] = fmaf(hv, wa.y, acc[1]);
        acc[2] = fmaf(hv, wa.z, acc[2]);
        acc[3] = fmaf(hv, wa.w, acc[3]);
        acc[4] = fmaf(hv, wb.x, acc[4]);
        acc[5] = fmaf(hv, wb.y, acc[5]);
        acc[6] = fmaf(hv, wb.z, acc[6]);
        acc[7] = fmaf(hv, wb.w, acc[7]);
    }
    #pragma unroll
    for (int k = 0; k < 8; k++) sred[w][e][k] = acc[k];
    __syncthreads();

    int re = t >> 3, rk = t & 7;
    float s = 0.f;
    #pragma unroll
    for (int ww = 0; ww < 8; ww++) s += sred[ww][re][rk];
    int ridx = blockIdx.x*32 + re;
    if (ridx <= TABN + 2) {
        float v = (ridx == TABN + 2) ? 0.f : s + b2[rk];
        out[(size_t)ridx*8 + rk] = v;
    }
}

// ---------------- 32x32-tile fp32 GEMM, 256 threads, in-CTA split-K x2 ----
// C = A[M,K] @ B[K,N] (+bias, opt relu/add). K%16==0, N%32==0.
// kg=0 handles k 0..7 of each 16-chunk, kg=1 handles k 8..15; combined via
// padded smem at the end. 2x4 outputs per kg=0 thread.
__global__ void __launch_bounds__(256) gemm_kernel(
        const float* __restrict__ A, const float* __restrict__ B,
        const float* __restrict__ bias, float* __restrict__ C,
        int M, int N, int K, int flags) {
    __shared__ __align__(16) float As[2][16][36];
    __shared__ __align__(16) float Bs[2][16][36];
    __shared__ float sred[128][9];
    int t  = threadIdx.x;
    int m0 = blockIdx.y << 5, n0 = blockIdx.x << 5;
    int arow = t >> 3, acol = (t & 7) << 1;   // A tile 32x16, float2/thread
    int brow = t >> 4, bcol = (t & 15) << 1;  // B tile 16x32, float2/thread
    int tx = t & 7;                           // col group (x4)
    int ty = (t >> 3) & 15;                   // row pair
    int kg = t >> 7;                          // k-split group 0/1
    float acc[2][4] = {};

    bool aval = (m0 + arow) < M;
    const float* Aptr = A + (size_t)(m0 + arow)*K + acol;
    const float* Bptr = B + (size_t)brow*N + n0 + bcol;

    float2 ra = aval ? *(const float2*)Aptr : make_float2(0.f, 0.f);
    float2 rb = *(const float2*)Bptr;
    int buf = 0;
    As[0][acol][arow] = ra.x; As[0][acol+1][arow] = ra.y;
    *(float2*)&Bs[0][brow][bcol] = rb;
    __syncthreads();

    for (int k0 = 16; ; k0 += 16) {
        bool more = (k0 < K);
        if (more) {
            ra = aval ? *(const float2*)(Aptr + k0) : make_float2(0.f, 0.f);
            rb = *(const float2*)(Bptr + (size_t)k0*N);
        }
        #pragma unroll
        for (int kk = 0; kk < 8; kk++) {
            int k = (kg << 3) + kk;
            float2 a = *(const float2*)&As[buf][k][ty<<1];
            float4 b = *(const float4*)&Bs[buf][k][tx<<2];
            acc[0][0] = fmaf(a.x, b.x, acc[0][0]);
            acc[0][1] = fmaf(a.x, b.y, acc[0][1]);
            acc[0][2] = fmaf(a.x, b.z, acc[0][2]);
            acc[0][3] = fmaf(a.x, b.w, acc[0][3]);
            acc[1][0] = fmaf(a.y, b.x, acc[1][0]);
            acc[1][1] = fmaf(a.y, b.y, acc[1][1]);
            acc[1][2] = fmaf(a.y, b.z, acc[1][2]);
            acc[1][3] = fmaf(a.y, b.w, acc[1][3]);
        }
        if (!more) break;
        buf ^= 1;
        As[buf][acol][arow] = ra.x; As[buf][acol+1][arow] = ra.y;
        *(float2*)&Bs[buf][brow][bcol] = rb;
        __syncthreads();
    }

    // combine k-split halves
    if (kg == 1) {
        float* r = sred[t & 127];
        r[0] = acc[0][0]; r[1] = acc[0][1]; r[2] = acc[0][2]; r[3] = acc[0][3];
        r[4] = acc[1][0]; r[5] = acc[1][1]; r[6] = acc[1][2]; r[7] = acc[1][3];
    }
    __syncthreads();
    if (kg == 0) {
        const float* r = sred[t];
        acc[0][0] += r[0]; acc[0][1] += r[1]; acc[0][2] += r[2]; acc[0][3] += r[3];
        acc[1][0] += r[4]; acc[1][1] += r[5]; acc[1][2] += r[6]; acc[1][3] += r[7];

        float4 bv = *(const float4*)(bias + n0 + (tx<<2));
        #pragma unroll
        for (int i = 0; i < 2; i++) {
            int m = m0 + (ty<<1) + i;
            if (m >= M) break;
            float4 v = make_float4(acc[i][0]+bv.x, acc[i][1]+bv.y,
                                   acc[i][2]+bv.z, acc[i][3]+bv.w);
            if (flags & FLAG_RELU) {
                v.x = fmaxf(v.x,0.f); v.y = fmaxf(v.y,0.f);
                v.z = fmaxf(v.z,0.f); v.w = fmaxf(v.w,0.f);
            }
            float4* cp = (float4*)(C + (size_t)m*N + n0 + (tx<<2));
            if (flags & FLAG_ADD) {
                float4 o = *cp;
                v.x += o.x; v.y += o.y; v.z += o.z; v.w += o.w;
            }
            *cp = v;
        }
    }
}

// ---------------- layernorm (one block per row) ----------------
__global__ void ln_kernel(const float* __restrict__ x, float* __restrict__ y,
                          const float* __restrict__ g, const float* __restrict__ b) {
    int row = blockIdx.x, t = threadIdx.x;     // 256 threads
    const float* xr = x + (size_t)row*DIMM;
    float v0 = xr[t], v1 = xr[t+256];
    float2 s = blockReduce2_256(v0+v1, v0*v0+v1*v1);
    float mean = s.x * (1.f/512.f);
    float inv  = rsqrtf(s.y*(1.f/512.f) - mean*mean + 1e-5f);
    y[(size_t)row*DIMM + t]       = (v0-mean)*inv*g[t]     + b[t];
    y[(size_t)row*DIMM + t + 256] = (v1-mean)*inv*g[t+256] + b[t+256];
}

// ---------------- QK^T scores + fused CPB bias ----------------
__global__ void __launch_bounds__(128) scores_kernel(const float* __restrict__ tab) {
    __shared__ __align__(16) float Qs[64][36];   // [d][i]
    __shared__ __align__(16) float Ks[64][68];   // [d][j]
    int h  = blockIdx.z;
    int i0 = blockIdx.y << 5, j0 = blockIdx.x << 6;
    int t  = threadIdx.x;

    {
        int r = t >> 2, c = (t & 3) << 4;
        const float* qp = g_qkv + (size_t)(i0+r)*QKV3 + h*HDIM + c;
        bool v = (i0 + r) < NTOK;
        #pragma unroll
        for (int q = 0; q < 4; q++) {
            float4 x = v ? *(const float4*)(qp + (q<<2)) : make_float4(0.f,0.f,0.f,0.f);
            int d = c + (q<<2);
            Qs[d  ][r] = x.x; Qs[d+1][r] = x.y;
            Qs[d+2][r] = x.z; Qs[d+3][r] = x.w;
        }
    }
    {
        int r = t >> 1, c = (t & 1) << 5;
        const float* kp = g_qkv + (size_t)(j0+r)*QKV3 + DIMM + h*HDIM + c;
        bool v = (j0 + r) < NTOK;
        #pragma unroll
        for (int q = 0; q < 8; q++) {
            float4 x = v ? *(const float4*)(kp + (q<<2)) : make_float4(0.f,0.f,0.f,0.f);
            int d = c + (q<<2);
            Ks[d  ][r] = x.x; Ks[d+1][r] = x.y;
            Ks[d+2][r] = x.z; Ks[d+3][r] = x.w;
        }
    }
    __syncthreads();

    int tx = t & 15, ty = t >> 4;
    float acc[4][4] = {};
    #pragma unroll 8
    for (int d = 0; d < 64; d++) {
        float4 a = *(const float4*)&Qs[d][ty<<2];
        float4 b = *(const float4*)&Ks[d][tx<<2];
        acc[0][0] = fmaf(a.x, b.x, acc[0][0]);
        acc[0][1] = fmaf(a.x, b.y, acc[0][1]);
        acc[0][2] = fmaf(a.x, b.z, acc[0][2]);
        acc[0][3] = fmaf(a.x, b.w, acc[0][3]);
        acc[1][0] = fmaf(a.y, b.x, acc[1][0]);
        acc[1][1] = fmaf(a.y, b.y, acc[1][1]);
        acc[1][2] = fmaf(a.y, b.z, acc[1][2]);
        acc[1][3] = fmaf(a.y, b.w, acc[1][3]);
        acc[2][0] = fmaf(a.z, b.x, acc[2][0]);
        acc[2][1] = fmaf(a.z, b.y, acc[2][1]);
        acc[2][2] = fmaf(a.z, b.z, acc[2][2]);
        acc[2][3] = fmaf(a.z, b.w, acc[2][3]);
        acc[3][0] = fmaf(a.w, b.x, acc[3][0]);
        acc[3][1] = fmaf(a.w, b.y, acc[3][1]);
        acc[3][2] = fmaf(a.w, b.z, acc[3][2]);
        acc[3][3] = fmaf(a.w, b.w, acc[3][3]);
    }

    #pragma unroll
    for (int qi = 0; qi < 4; qi++) {
        int i = i0 + (ty<<2) + qi;
        if (i >= NTOK) break;
        #pragma unroll
        for (int qj = 0; qj < 4; qj++) {
            int j = j0 + (tx<<2) + qj;
            if (j < NTOK) {
                size_t p = (size_t)i*NTOK + j;
                float pos = g_angpos[p];
                int   ip  = (int)pos;
                float f   = pos - (float)ip;
                const float* r0 = tab + (size_t)ip*8 + h;
                float bias = r0[0] + f*(r0[8] - r0[0]);
                g_attn[(size_t)h*NTOK*NTOK + p] = fmaf(0.125f, acc[qi][qj], bias);
            }
        }
    }
}

// ---------------- fused softmax + attn@V (per-head, 32 i-rows) ------------
__global__ void __launch_bounds__(256) softav_kernel() {
    __shared__ float sa[32][33];
    __shared__ __align__(16) float sv[32][68];
    __shared__ float smx[32], sinv[32];
    int h  = blockIdx.y;
    int i0 = blockIdx.x << 5;
    int t  = threadIdx.x;

    {
        int row = t >> 3, k8 = t & 7;
        int gi  = i0 + row;
        int cgi = gi < NTOK ? gi : NTOK - 1;
        const float* arow = g_attn + ((size_t)h*NTOK + cgi)*NTOK;
        float m = -1e30f;
        for (int j = k8; j < NTOK; j += 8) m = fmaxf(m, arow[j]);
        #pragma unroll
        for (int o = 1; o < 8; o <<= 1)
            m = fmaxf(m, __shfl_xor_sync(0xffffffffu, m, o));
        float s = 0.f;
        for (int j = k8; j < NTOK; j += 8) s += __expf(arow[j] - m);
        #pragma unroll
        for (int o = 1; o < 8; o <<= 1)
            s += __shfl_xor_sync(0xffffffffu, s, o);
        if (k8 == 0) { smx[row] = m; sinv[row] = 1.f / s; }
    }
    __syncthreads();

    int tx = t & 15, ty = t >> 4;
    int d4 = tx << 2;
    int ar = t >> 3, ac = (t & 7) << 2;
    int vr = t >> 3, vc = (t & 7) << 3;
    float mrow = smx[ar];
    float acc[2][4] = {};
    for (int j0 = 0; j0 < NTOK; j0 += 32) {
        #pragma unroll
        for (int q = 0; q < 4; q++) {
            int i = i0 + ar, j = j0 + ac + q;
            float e = 0.f;
            if (i < NTOK && j < NTOK)
                e = __expf(g_attn[((size_t)h*NTOK + i)*NTOK + j] - mrow);
            sa[ar][ac+q] = e;
        }
        {
            const float* vp = g_qkv + (size_t)(j0+vr)*QKV3 + 2*DIMM + h*HDIM + vc;
            bool vi = (j0 + vr < NTOK);
            float4 z = make_float4(0.f,0.f,0.f,0.f);
            float4 v0 = vi ? *(const float4*)vp       : z;
            float4 v1 = vi ? *(const float4*)(vp + 4) : z;
            *(float4*)&sv[vr][vc]   = v0;
            *(float4*)&sv[vr][vc+4] = v1;
        }
        __syncthreads();
        #pragma unroll
        for (int j = 0; j < 32; j++) {
            float4 vv = *(const float4*)&sv[j][d4];
            float a0 = sa[ty][j], a1 = sa[ty+16][j];
            acc[0][0] = fmaf(a0, vv.x, acc[0][0]);
            acc[0][1] = fmaf(a0, vv.y, acc[0][1]);
            acc[0][2] = fmaf(a0, vv.z, acc[0][2]);
            acc[0][3] = fmaf(a0, vv.w, acc[0][3]);
            acc[1][0] = fmaf(a1, vv.x, acc[1][0]);
            acc[1][1] = fmaf(a1, vv.y, acc[1][1]);
            acc[1][2] = fmaf(a1, vv.z, acc[1][2]);
            acc[1][3] = fmaf(a1, vv.w, acc[1][3]);
        }
        __syncthreads();
    }
    #pragma unroll
    for (int q = 0; q < 2; q++) {
        int i = i0 + ty + (q<<4);
        if (i < NTOK) {
            float inv = sinv[ty + (q<<4)];
            *(float4*)(g_ao + (size_t)i*DIMM + h*HDIM + d4) =
                make_float4(acc[q][0]*inv, acc[q][1]*inv,
                            acc[q][2]*inv, acc[q][3]*inv);
        }
    }
}

// ---------------- final: LN(row 0) -> fc2 -> out[2] ----------------
__global__ void final_kernel(const float* __restrict__ g, const float* __restrict__ b,
                             const float* __restrict__ w, const float* __restrict__ bias,
                             float* __restrict__ out) {
    int t = threadIdx.x;                  // 256 threads
    float v0 = g_h[t], v1 = g_h[t+256];
    float2 s = blockReduce2_256(v0+v1, v0*v0+v1*v1);
    float mean = s.x * (1.f/512.f);
    float inv  = rsqrtf(s.y*(1.f/512.f) - mean*mean + 1e-5f);
    float l0 = (v0-mean)*inv*g[t]     + b[t];
    float l1 = (v1-mean)*inv*g[t+256] + b[t+256];
    float p0 = l0*w[t*2]   + l1*w[(t+256)*2];
    float p1 = l0*w[t*2+1] + l1*w[(t+256)*2+1];
    float2 sp = blockReduce2_256(p0, p1);
    if (t == 0) { out[0] = sp.x + bias[0]; out[1] = sp.y + bias[1]; }
}

// ---------------- launch ----------------
extern "C" void kernel_launch(void* const* d_in, const int* in_sizes, int n_in,
                              void* d_out, int out_size) {
    const float* h_in   = (const float*)d_in[0];
    const float* coords = (const float*)d_in[1];
    const float* fc1_w  = (const float*)d_in[2];
    const float* fc1_b  = (const float*)d_in[3];
    const float* cls    = (const float*)d_in[4];
    const float* norm_g = (const float*)d_in[25];
    const float* norm_b = (const float*)d_in[26];
    const float* fc2_w  = (const float*)d_in[27];
    const float* fc2_b  = (const float*)d_in[28];

    float *p_h, *p_ln, *p_qkv, *p_ao, *p_tab[2];
    cudaGetSymbolAddress((void**)&p_h,      g_h);
    cudaGetSymbolAddress((void**)&p_ln,     g_ln);
    cudaGetSymbolAddress((void**)&p_qkv,    g_qkv);
    cudaGetSymbolAddress((void**)&p_ao,     g_ao);
    cudaGetSymbolAddress((void**)&p_tab[0], g_table0);
    cudaGetSymbolAddress((void**)&p_tab[1], g_table1);

    setup_kernel<<<4, 256>>>(cls, coords);
    angpos_kernel<<<(NPAIR + 255)/256, 256>>>();
    cpb_table_kernel<<<dim3((TABN + 3 + 31)/32, 2), 256>>>(
        (const float*)d_in[7],  (const float*)d_in[8],
        (const float*)d_in[9],  (const float*)d_in[10], p_tab[0],
        (const float*)d_in[17], (const float*)d_in[18],
        (const float*)d_in[19], (const float*)d_in[20], p_tab[1]);
    // fc1 + relu into rows 1..400 of residual stream
    gemm_kernel<<<dim3(DIMM/32, (NPT+31)/32), 256>>>(
        h_in, fc1_w, fc1_b, p_h + DIMM, NPT, DIMM, 1024, FLAG_RELU);

    for (int L = 0; L < 2; L++) {
        const float* lp[10];
        for (int q = 0; q < 10; q++) lp[q] = (const float*)d_in[5 + L*10 + q];
        const float* ln_g   = lp[0]; const float* ln_b   = lp[1];
        const float* qkv_w  = lp[6]; const float* qkv_b  = lp[7];
        const float* proj_w = lp[8]; const float* proj_b = lp[9];

        ln_kernel<<<NTOK, 256>>>(p_h, p_ln, ln_g, ln_b);
        gemm_kernel<<<dim3(QKV3/32, (NTOK+31)/32), 256>>>(
            p_ln, qkv_w, qkv_b, p_qkv, NTOK, QKV3, DIMM, 0);
        scores_kernel<<<dim3(7, 13, NHEAD), 128>>>(p_tab[L]);
        softav_kernel<<<dim3(13, NHEAD), 256>>>();
        gemm_kernel<<<dim3(DIMM/32, (NTOK+31)/32), 256>>>(
            p_ao, proj_w, proj_b, p_h, NTOK, DIMM, DIMM, FLAG_ADD);
    }

    final_kernel<<<1, 256>>>(norm_g, norm_b, fc2_w, fc2_b, (float*)d_out);
}

// round 10
// speedup vs baseline: 1.4364x; 1.0270x over previous
#include <cuda_runtime.h>
#include <math.h>

#define NTOK 401
#define NPT  400
#define DIMM 512
#define NHEAD 8
#define HDIM 64
#define QKV3 1536
#define CPBH 512
#define NPAIR (NTOK*NTOK)
#define TABN 4096
#define PI_F 3.14159265358979323846f
#define FLAG_RELU 1
#define FLAG_ADD  2
#define FLAG_RAW  4

// ---------------- scratch (alloc-free, __device__ globals) ----------------
__device__ float  g_h[NTOK*DIMM];          // residual stream
__device__ float  g_ln[NTOK*DIMM];         // layernorm output
__device__ float  g_qkv[NTOK*QKV3];        // fused qkv
__device__ float  g_attn[NHEAD*NTOK*NTOK]; // attention logits (5.1 MB)
__device__ float  g_ao[NTOK*DIMM];         // attention output (pre-proj)
__device__ float  g_part[4*NTOK*DIMM];     // split-K partials (3.2 MB)
__device__ float  g_angpos[NPAIR];         // table position per pair (both layers)
__device__ float  g_coords[NTOK*2];
__device__ float  g_table0[(TABN+4)*8];    // layer-1 bias table
__device__ float  g_table1[(TABN+4)*8];    // layer-2 bias table

// ---------------- small helpers ----------------
__device__ __forceinline__ float2 blockReduce2_256(float a, float b) {
    __shared__ float sa[8], sb[8];
    __syncthreads();
    #pragma unroll
    for (int o = 16; o > 0; o >>= 1) {
        a += __shfl_xor_sync(0xffffffffu, a, o);
        b += __shfl_xor_sync(0xffffffffu, b, o);
    }
    int w = threadIdx.x >> 5;
    if ((threadIdx.x & 31) == 0) { sa[w] = a; sb[w] = b; }
    __syncthreads();
    a = sa[0]+sa[1]+sa[2]+sa[3]+sa[4]+sa[5]+sa[6]+sa[7];
    b = sb[0]+sb[1]+sb[2]+sb[3]+sb[4]+sb[5]+sb[6]+sb[7];
    return make_float2(a, b);
}

// ---------------- setup: CLS row + coords (CLS coord = 0) ----------------
__global__ void setup_kernel(const float* __restrict__ cls,
                             const float* __restrict__ coords) {
    int t = blockIdx.x*blockDim.x + threadIdx.x;
    if (t < DIMM)  g_h[t] = cls[t];
    if (t < 2)     g_coords[t] = 0.f;
    if (t < NPT*2) g_coords[2+t] = coords[t];
}

// ---------------- per-pair angle table position ----------------
__global__ void angpos_kernel() {
    int p = blockIdx.x*blockDim.x + threadIdx.x;
    if (p >= NPAIR) return;
    int i = p / NTOK, j = p - i*NTOK;
    float pos;
    if (i == j) {
        pos = (float)(TABN + 1);           // diag: dir = (0,0) special row
    } else {
        float dx = g_coords[2*i]   - g_coords[2*j];
        float dy = g_coords[2*i+1] - g_coords[2*j+1];
        float th = atan2f(dy, dx);
        pos = (th + PI_F) * ((float)TABN / (2.0f*PI_F));
        pos = fminf(fmaxf(pos, 0.f), (float)TABN);
    }
    g_angpos[p] = pos;
}

// ---------------- build CPB bias tables (both layers, grid.y selects) ----
__global__ void __launch_bounds__(256) cpb_table_kernel(
        const float* __restrict__ w1a, const float* __restrict__ b1a,
        const float* __restrict__ w2a, const float* __restrict__ b2a,
        float* __restrict__ outa,
        const float* __restrict__ w1b, const float* __restrict__ b1b,
        const float* __restrict__ w2b, const float* __restrict__ b2b,
        float* __restrict__ outb) {
    const float* w1 = blockIdx.y ? w1b : w1a;
    const float* b1 = blockIdx.y ? b1b : b1a;
    const float* w2 = blockIdx.y ? w2b : w2a;
    const float* b2 = blockIdx.y ? b2b : b2a;
    float*      out = blockIdx.y ? outb : outa;

    __shared__ float swx[CPBH], swy[CPBH], sbb[CPBH];
    __shared__ __align__(16) float sw2[CPBH*8];
    __shared__ float sred[8][32][9];
    int t = threadIdx.x;
    for (int c = t; c < CPBH; c += 256) {
        swx[c] = w1[c]; swy[c] = w1[CPBH + c]; sbb[c] = b1[c];
    }
    for (int c = t; c < CPBH*2; c += 256)
        *(float4*)(sw2 + c*4) = *(const float4*)(w2 + c*4);
    __syncthreads();

    int e = t & 31;
    int w = t >> 5;
    int idx = blockIdx.x*32 + e;
    float ux = 0.f, uy = 0.f;
    if (idx <= TABN) {
        float th = -PI_F + (2.0f*PI_F) * ((float)idx / (float)TABN);
        sincosf(th, &uy, &ux);
    }
    float acc[8] = {0.f,0.f,0.f,0.f,0.f,0.f,0.f,0.f};
    int c0 = w << 6;
    #pragma unroll 8
    for (int cc = 0; cc < 64; cc++) {
        int c = c0 + cc;
        float hv = fmaf(ux, swx[c], fmaf(uy, swy[c], sbb[c]));
        hv = fmaxf(hv, 0.f);
        float4 wa = *(const float4*)(sw2 + (c<<3));
        float4 wb = *(const float4*)(sw2 + (c<<3) + 4);
        acc[0] = fmaf(hv, wa.x, acc[0]);
        acc[1] = fmaf(hv, wa.y, acc[1]);
        acc[2] = fmaf(hv, wa.z, acc[2]);
        acc[3] = fmaf(hv, wa.w, acc[3]);
        acc[4] = fmaf(hv, wb.x, acc[4]);
        acc[5] = fmaf(hv, wb.y, acc[5]);
        acc[6] = fmaf(hv, wb.z, acc[6]);
        acc[7] = fmaf(hv, wb.w, acc[7]);
    }
    #pragma unroll
    for (int k = 0; k < 8; k++) sred[w][e][k] = acc[k];
    __syncthreads();

    int re = t >> 3, rk = t & 7;
    float s = 0.f;
    #pragma unroll
    for (int ww = 0; ww < 8; ww++) s += sred[ww][re][rk];
    int ridx = blockIdx.x*32 + re;
    if (ridx <= TABN + 2) {
        float v = (ridx == TABN + 2) ? 0.f : s + b2[rk];
        out[(size_t)ridx*8 + rk] = v;
    }
}

// ---------------- 32x32-tile fp32 GEMM, 256 threads, in-CTA split-K x2 ----
// Additionally CTA-level split-K via blockIdx.z: slice z covers
// k in [z*K, (z+1)*K); raw partials go to C + z*M*N when FLAG_RAW.
__global__ void __launch_bounds__(256) gemm_kernel(
        const float* __restrict__ A, int lda,
        const float* __restrict__ B, int ldb,
        const float* __restrict__ bias,
        float* __restrict__ C, int ldc,
        int M, int N, int K, int flags) {
    __shared__ __align__(16) float As[2][16][36];
    __shared__ __align__(16) float Bs[2][16][36];
    __shared__ float sred[128][9];
    int t  = threadIdx.x;
    int m0 = blockIdx.y << 5, n0 = blockIdx.x << 5;
    int zi = blockIdx.z;
    const float* Az = A + (size_t)zi*K;            // k-offset within row
    const float* Bz = B + (size_t)zi*K*ldb;
    float* Cz = C + (size_t)zi*M*N;                // partial-slice base (RAW)
    int arow = t >> 3, acol = (t & 7) << 1;
    int brow = t >> 4, bcol = (t & 15) << 1;
    int tx = t & 7;
    int ty = (t >> 3) & 15;
    int kg = t >> 7;
    float acc[2][4] = {};

    bool aval = (m0 + arow) < M;
    const float* Aptr = Az + (size_t)(m0 + arow)*lda + acol;
    const float* Bptr = Bz + (size_t)brow*ldb + n0 + bcol;

    float2 ra = aval ? *(const float2*)Aptr : make_float2(0.f, 0.f);
    float2 rb = *(const float2*)Bptr;
    int buf = 0;
    As[0][acol][arow] = ra.x; As[0][acol+1][arow] = ra.y;
    *(float2*)&Bs[0][brow][bcol] = rb;
    __syncthreads();

    for (int k0 = 16; ; k0 += 16) {
        bool more = (k0 < K);
        if (more) {
            ra = aval ? *(const float2*)(Aptr + k0) : make_float2(0.f, 0.f);
            rb = *(const float2*)(Bptr + (size_t)k0*ldb);
        }
        #pragma unroll
        for (int kk = 0; kk < 8; kk++) {
            int k = (kg << 3) + kk;
            float2 a = *(const float2*)&As[buf][k][ty<<1];
            float4 b = *(const float4*)&Bs[buf][k][tx<<2];
            acc[0][0] = fmaf(a.x, b.x, acc[0][0]);
            acc[0][1] = fmaf(a.x, b.y, acc[0][1]);
            acc[0][2] = fmaf(a.x, b.z, acc[0][2]);
            acc[0][3] = fmaf(a.x, b.w, acc[0][3]);
            acc[1][0] = fmaf(a.y, b.x, acc[1][0]);
            acc[1][1] = fmaf(a.y, b.y, acc[1][1]);
            acc[1][2] = fmaf(a.y, b.z, acc[1][2]);
            acc[1][3] = fmaf(a.y, b.w, acc[1][3]);
        }
        if (!more) break;
        buf ^= 1;
        As[buf][acol][arow] = ra.x; As[buf][acol+1][arow] = ra.y;
        *(float2*)&Bs[buf][brow][bcol] = rb;
        __syncthreads();
    }

    // combine in-CTA k-split halves
    if (kg == 1) {
        float* r = sred[t & 127];
        r[0] = acc[0][0]; r[1] = acc[0][1]; r[2] = acc[0][2]; r[3] = acc[0][3];
        r[4] = acc[1][0]; r[5] = acc[1][1]; r[6] = acc[1][2]; r[7] = acc[1][3];
    }
    __syncthreads();
    if (kg == 0) {
        const float* r = sred[t];
        acc[0][0] += r[0]; acc[0][1] += r[1]; acc[0][2] += r[2]; acc[0][3] += r[3];
        acc[1][0] += r[4]; acc[1][1] += r[5]; acc[1][2] += r[6]; acc[1][3] += r[7];

        if (flags & FLAG_RAW) {
            #pragma unroll
            for (int i = 0; i < 2; i++) {
                int m = m0 + (ty<<1) + i;
                if (m >= M) break;
                *(float4*)(Cz + (size_t)m*ldc + n0 + (tx<<2)) =
                    make_float4(acc[i][0], acc[i][1], acc[i][2], acc[i][3]);
            }
            return;
        }
        float4 bv = *(const float4*)(bias + n0 + (tx<<2));
        #pragma unroll
        for (int i = 0; i < 2; i++) {
            int m = m0 + (ty<<1) + i;
            if (m >= M) break;
            float4 v = make_float4(acc[i][0]+bv.x, acc[i][1]+bv.y,
                                   acc[i][2]+bv.z, acc[i][3]+bv.w);
            if (flags & FLAG_RELU) {
                v.x = fmaxf(v.x,0.f); v.y = fmaxf(v.y,0.f);
                v.z = fmaxf(v.z,0.f); v.w = fmaxf(v.w,0.f);
            }
            float4* cp = (float4*)(C + (size_t)m*ldc + n0 + (tx<<2));
            if (flags & FLAG_ADD) {
                float4 o = *cp;
                v.x += o.x; v.y += o.y; v.z += o.z; v.w += o.w;
            }
            *cp = v;
        }
    }
}

// ---------------- split-K reduce: C = op(sum_s part[s] + bias) ------------
__global__ void __launch_bounds__(256) reduce_kernel(
        const float* __restrict__ part, const float* __restrict__ bias,
        float* __restrict__ C, int MN, int N, int S, int flags) {
    int idx = (blockIdx.x*256 + threadIdx.x) << 2;
    if (idx >= MN) return;
    float4 v = *(const float4*)(part + idx);
    for (int s = 1; s < S; s++) {
        float4 p = *(const float4*)(part + (size_t)s*MN + idx);
        v.x += p.x; v.y += p.y; v.z += p.z; v.w += p.w;
    }
    float4 bv = *(const float4*)(bias + (idx % N));
    v.x += bv.x; v.y += bv.y; v.z += bv.z; v.w += bv.w;
    if (flags & FLAG_RELU) {
        v.x = fmaxf(v.x,0.f); v.y = fmaxf(v.y,0.f);
        v.z = fmaxf(v.z,0.f); v.w = fmaxf(v.w,0.f);
    }
    float4* cp = (float4*)(C + idx);
    if (flags & FLAG_ADD) {
        float4 o = *cp;
        v.x += o.x; v.y += o.y; v.z += o.z; v.w += o.w;
    }
    *cp = v;
}

// ---------------- layernorm (one block per row) ----------------
__global__ void ln_kernel(const float* __restrict__ x, float* __restrict__ y,
                          const float* __restrict__ g, const float* __restrict__ b) {
    int row = blockIdx.x, t = threadIdx.x;     // 256 threads
    const float* xr = x + (size_t)row*DIMM;
    float v0 = xr[t], v1 = xr[t+256];
    float2 s = blockReduce2_256(v0+v1, v0*v0+v1*v1);
    float mean = s.x * (1.f/512.f);
    float inv  = rsqrtf(s.y*(1.f/512.f) - mean*mean + 1e-5f);
    y[(size_t)row*DIMM + t]       = (v0-mean)*inv*g[t]     + b[t];
    y[(size_t)row*DIMM + t + 256] = (v1-mean)*inv*g[t+256] + b[t+256];
}

// ---------------- QK^T scores + fused CPB bias ----------------
__global__ void __launch_bounds__(128) scores_kernel(const float* __restrict__ tab) {
    __shared__ __align__(16) float Qs[64][36];   // [d][i]
    __shared__ __align__(16) float Ks[64][68];   // [d][j]
    int h  = blockIdx.z;
    int i0 = blockIdx.y << 5, j0 = blockIdx.x << 6;
    int t  = threadIdx.x;

    {
        int r = t >> 2, c = (t & 3) << 4;
        const float* qp = g_qkv + (size_t)(i0+r)*QKV3 + h*HDIM + c;
        bool v = (i0 + r) < NTOK;
        #pragma unroll
        for (int q = 0; q < 4; q++) {
            float4 x = v ? *(const float4*)(qp + (q<<2)) : make_float4(0.f,0.f,0.f,0.f);
            int d = c + (q<<2);
            Qs[d  ][r] = x.x; Qs[d+1][r] = x.y;
            Qs[d+2][r] = x.z; Qs[d+3][r] = x.w;
        }
    }
    {
        int r = t >> 1, c = (t & 1) << 5;
        const float* kp = g_qkv + (size_t)(j0+r)*QKV3 + DIMM + h*HDIM + c;
        bool v = (j0 + r) < NTOK;
        #pragma unroll
        for (int q = 0; q < 8; q++) {
            float4 x = v ? *(const float4*)(kp + (q<<2)) : make_float4(0.f,0.f,0.f,0.f);
            int d = c + (q<<2);
            Ks[d  ][r] = x.x; Ks[d+1][r] = x.y;
            Ks[d+2][r] = x.z; Ks[d+3][r] = x.w;
        }
    }
    __syncthreads();

    int tx = t & 15, ty = t >> 4;
    float acc[4][4] = {};
    #pragma unroll 8
    for (int d = 0; d < 64; d++) {
        float4 a = *(const float4*)&Qs[d][ty<<2];
        float4 b = *(const float4*)&Ks[d][tx<<2];
        acc[0][0] = fmaf(a.x, b.x, acc[0][0]);
        acc[0][1] = fmaf(a.x, b.y, acc[0][1]);
        acc[0][2] = fmaf(a.x, b.z, acc[0][2]);
        acc[0][3] = fmaf(a.x, b.w, acc[0][3]);
        acc[1][0] = fmaf(a.y, b.x, acc[1][0]);
        acc[1][1] = fmaf(a.y, b.y, acc[1][1]);
        acc[1][2] = fmaf(a.y, b.z, acc[1][2]);
        acc[1][3] = fmaf(a.y, b.w, acc[1][3]);
        acc[2][0] = fmaf(a.z, b.x, acc[2][0]);
        acc[2][1] = fmaf(a.z, b.y, acc[2][1]);
        acc[2][2] = fmaf(a.z, b.z, acc[2][2]);
        acc[2][3] = fmaf(a.z, b.w, acc[2][3]);
        acc[3][0] = fmaf(a.w, b.x, acc[3][0]);
        acc[3][1] = fmaf(a.w, b.y, acc[3][1]);
        acc[3][2] = fmaf(a.w, b.z, acc[3][2]);
        acc[3][3] = fmaf(a.w, b.w, acc[3][3]);
    }

    #pragma unroll
    for (int qi = 0; qi < 4; qi++) {
        int i = i0 + (ty<<2) + qi;
        if (i >= NTOK) break;
        #pragma unroll
        for (int qj = 0; qj < 4; qj++) {
            int j = j0 + (tx<<2) + qj;
            if (j < NTOK) {
                size_t p = (size_t)i*NTOK + j;
                float pos = g_angpos[p];
                int   ip  = (int)pos;
                float f   = pos - (float)ip;
                const float* r0 = tab + (size_t)ip*8 + h;
                float bias = r0[0] + f*(r0[8] - r0[0]);
                g_attn[(size_t)h*NTOK*NTOK + p] = fmaf(0.125f, acc[qi][qj], bias);
            }
        }
    }
}

// ---------------- fused softmax + attn@V (per-head, 32 i-rows) ------------
__global__ void __launch_bounds__(256) softav_kernel() {
    __shared__ float sa[32][33];
    __shared__ __align__(16) float sv[32][68];
    __shared__ float smx[32], sinv[32];
    int h  = blockIdx.y;
    int i0 = blockIdx.x << 5;
    int t  = threadIdx.x;

    {
        int row = t >> 3, k8 = t & 7;
        int gi  = i0 + row;
        int cgi = gi < NTOK ? gi : NTOK - 1;
        const float* arow = g_attn + ((size_t)h*NTOK + cgi)*NTOK;
        float m = -1e30f;
        for (int j = k8; j < NTOK; j += 8) m = fmaxf(m, arow[j]);
        #pragma unroll
        for (int o = 1; o < 8; o <<= 1)
            m = fmaxf(m, __shfl_xor_sync(0xffffffffu, m, o));
        float s = 0.f;
        for (int j = k8; j < NTOK; j += 8) s += __expf(arow[j] - m);
        #pragma unroll
        for (int o = 1; o < 8; o <<= 1)
            s += __shfl_xor_sync(0xffffffffu, s, o);
        if (k8 == 0) { smx[row] = m; sinv[row] = 1.f / s; }
    }
    __syncthreads();

    int tx = t & 15, ty = t >> 4;
    int d4 = tx << 2;
    int ar = t >> 3, ac = (t & 7) << 2;
    int vr = t >> 3, vc = (t & 7) << 3;
    float mrow = smx[ar];
    float acc[2][4] = {};
    for (int j0 = 0; j0 < NTOK; j0 += 32) {
        #pragma unroll
        for (int q = 0; q < 4; q++) {
            int i = i0 + ar, j = j0 + ac + q;
            float e = 0.f;
            if (i < NTOK && j < NTOK)
                e = __expf(g_attn[((size_t)h*NTOK + i)*NTOK + j] - mrow);
            sa[ar][ac+q] = e;
        }
        {
            const float* vp = g_qkv + (size_t)(j0+vr)*QKV3 + 2*DIMM + h*HDIM + vc;
            bool vi = (j0 + vr < NTOK);
            float4 z = make_float4(0.f,0.f,0.f,0.f);
            float4 v0 = vi ? *(const float4*)vp       : z;
            float4 v1 = vi ? *(const float4*)(vp + 4) : z;
            *(float4*)&sv[vr][vc]   = v0;
            *(float4*)&sv[vr][vc+4] = v1;
        }
        __syncthreads();
        #pragma unroll
        for (int j = 0; j < 32; j++) {
            float4 vv = *(const float4*)&sv[j][d4];
            float a0 = sa[ty][j], a1 = sa[ty+16][j];
            acc[0][0] = fmaf(a0, vv.x, acc[0][0]);
            acc[0][1] = fmaf(a0, vv.y, acc[0][1]);
            acc[0][2] = fmaf(a0, vv.z, acc[0][2]);
            acc[0][3] = fmaf(a0, vv.w, acc[0][3]);
            acc[1][0] = fmaf(a1, vv.x, acc[1][0]);
            acc[1][1] = fmaf(a1, vv.y, acc[1][1]);
            acc[1][2] = fmaf(a1, vv.z, acc[1][2]);
            acc[1][3] = fmaf(a1, vv.w, acc[1][3]);
        }
        __syncthreads();
    }
    #pragma unroll
    for (int q = 0; q < 2; q++) {
        int i = i0 + ty + (q<<4);
        if (i < NTOK) {
            float inv = sinv[ty + (q<<4)];
            *(float4*)(g_ao + (size_t)i*DIMM + h*HDIM + d4) =
                make_float4(acc[q][0]*inv, acc[q][1]*inv,
                            acc[q][2]*inv, acc[q][3]*inv);
        }
    }
}

// ---------------- final: LN(row 0) -> fc2 -> out[2] ----------------
__global__ void final_kernel(const float* __restrict__ g, const float* __restrict__ b,
                             const float* __restrict__ w, const float* __restrict__ bias,
                             float* __restrict__ out) {
    int t = threadIdx.x;                  // 256 threads
    float v0 = g_h[t], v1 = g_h[t+256];
    float2 s = blockReduce2_256(v0+v1, v0*v0+v1*v1);
    float mean = s.x * (1.f/512.f);
    float inv  = rsqrtf(s.y*(1.f/512.f) - mean*mean + 1e-5f);
    float l0 = (v0-mean)*inv*g[t]     + b[t];
    float l1 = (v1-mean)*inv*g[t+256] + b[t+256];
    float p0 = l0*w[t*2]   + l1*w[(t+256)*2];
    float p1 = l0*w[t*2+1] + l1*w[(t+256)*2+1];
    float2 sp = blockReduce2_256(p0, p1);
    if (t == 0) { out[0] = sp.x + bias[0]; out[1] = sp.y + bias[1]; }
}

// ---------------- launch ----------------
extern "C" void kernel_launch(void* const* d_in, const int* in_sizes, int n_in,
                              void* d_out, int out_size) {
    const float* h_in   = (const float*)d_in[0];
    const float* coords = (const float*)d_in[1];
    const float* fc1_w  = (const float*)d_in[2];
    const float* fc1_b  = (const float*)d_in[3];
    const float* cls    = (const float*)d_in[4];
    const float* norm_g = (const float*)d_in[25];
    const float* norm_b = (const float*)d_in[26];
    const float* fc2_w  = (const float*)d_in[27];
    const float* fc2_b  = (const float*)d_in[28];

    float *p_h, *p_ln, *p_qkv, *p_ao, *p_part, *p_tab[2];
    cudaGetSymbolAddress((void**)&p_h,      g_h);
    cudaGetSymbolAddress((void**)&p_ln,     g_ln);
    cudaGetSymbolAddress((void**)&p_qkv,    g_qkv);
    cudaGetSymbolAddress((void**)&p_ao,     g_ao);
    cudaGetSymbolAddress((void**)&p_part,   g_part);
    cudaGetSymbolAddress((void**)&p_tab[0], g_table0);
    cudaGetSymbolAddress((void**)&p_tab[1], g_table1);

    setup_kernel<<<4, 256>>>(cls, coords);
    angpos_kernel<<<(NPAIR + 255)/256, 256>>>();
    cpb_table_kernel<<<dim3((TABN + 3 + 31)/32, 2), 256>>>(
        (const float*)d_in[7],  (const float*)d_in[8],
        (const float*)d_in[9],  (const float*)d_in[10], p_tab[0],
        (const float*)d_in[17], (const float*)d_in[18],
        (const float*)d_in[19], (const float*)d_in[20], p_tab[1]);

    // fc1: split-K x4 over CTAs (K=1024 -> 4x256), then reduce+bias+relu
    gemm_kernel<<<dim3(DIMM/32, (NPT+31)/32, 4), 256>>>(
        h_in, 1024, fc1_w, DIMM, (const float*)0,
        p_part, DIMM, NPT, DIMM, 256, FLAG_RAW);
    reduce_kernel<<<(NPT*DIMM/4 + 255)/256, 256>>>(
        p_part, fc1_b, p_h + DIMM, NPT*DIMM, DIMM, 4, FLAG_RELU);

    for (int L = 0; L < 2; L++) {
        const float* lp[10];
        for (int q = 0; q < 10; q++) lp[q] = (const float*)d_in[5 + L*10 + q];
        const float* ln_g   = lp[0]; const float* ln_b   = lp[1];
        const float* qkv_w  = lp[6]; const float* qkv_b  = lp[7];
        const float* proj_w = lp[8]; const float* proj_b = lp[9];

        ln_kernel<<<NTOK, 256>>>(p_h, p_ln, ln_g, ln_b);
        gemm_kernel<<<dim3(QKV3/32, (NTOK+31)/32, 1), 256>>>(
            p_ln, DIMM, qkv_w, QKV3, qkv_b, p_qkv, QKV3, NTOK, QKV3, DIMM, 0);
        scores_kernel<<<dim3(7, 13, NHEAD), 128>>>(p_tab[L]);
        softav_kernel<<<dim3(13, NHEAD), 256>>>();
        // proj: split-K x2 over CTAs (K=512 -> 2x256), reduce+bias+residual
        gemm_kernel<<<dim3(DIMM/32, (NTOK+31)/32, 2), 256>>>(
            p_ao, DIMM, proj_w, DIMM, (const float*)0,
            p_part, DIMM, NTOK, DIMM, 256, FLAG_RAW);
        reduce_kernel<<<(NTOK*DIMM/4 + 255)/256, 256>>>(
            p_part, proj_b, p_h, NTOK*DIMM, DIMM, 2, FLAG_ADD);
    }

    final_kernel<<<1, 256>>>(norm_g, norm_b, fc2_w, fc2_b, (float*)d_out);
}

// round 11
// speedup vs baseline: 1.6348x; 1.1381x over previous
#include <cuda_runtime.h>
#include <math.h>

#define NTOK 401
#define NPT  400
#define DIMM 512
#define NHEAD 8
#define HDIM 64
#define QKV3 1536
#define CPBH 512
#define NPAIR (NTOK*NTOK)
#define TABN 4096
#define PI_F 3.14159265358979323846f
#define FLAG_RELU 1
#define FLAG_ADD  2
#define FLAG_RAW  4

// ---------------- scratch (alloc-free, __device__ globals) ----------------
__device__ float  g_h[NTOK*DIMM];          // residual stream
__device__ float  g_ln[NTOK*DIMM];         // layernorm output
__device__ float  g_qkv[NTOK*QKV3];        // fused qkv
__device__ float  g_attn[NHEAD*NTOK*NTOK]; // attention logits (5.1 MB)
__device__ float  g_ao[NTOK*DIMM];         // attention output (pre-proj)
__device__ float  g_part[2*NTOK*QKV3];     // split-K partials (4.9 MB)
__device__ float  g_angpos[NPAIR];         // table position per pair (both layers)
__device__ float  g_coords[NTOK*2];
__device__ float  g_table0[(TABN+4)*8];    // layer-1 bias table
__device__ float  g_table1[(TABN+4)*8];    // layer-2 bias table

// ---------------- small helpers ----------------
__device__ __forceinline__ float2 blockReduce2_256(float a, float b) {
    __shared__ float sa[8], sb[8];
    __syncthreads();
    #pragma unroll
    for (int o = 16; o > 0; o >>= 1) {
        a += __shfl_xor_sync(0xffffffffu, a, o);
        b += __shfl_xor_sync(0xffffffffu, b, o);
    }
    int w = threadIdx.x >> 5;
    if ((threadIdx.x & 31) == 0) { sa[w] = a; sb[w] = b; }
    __syncthreads();
    a = sa[0]+sa[1]+sa[2]+sa[3]+sa[4]+sa[5]+sa[6]+sa[7];
    b = sb[0]+sb[1]+sb[2]+sb[3]+sb[4]+sb[5]+sb[6]+sb[7];
    return make_float2(a, b);
}

// ---------------- setup: CLS row + coords (CLS coord = 0) ----------------
__global__ void setup_kernel(const float* __restrict__ cls,
                             const float* __restrict__ coords) {
    int t = blockIdx.x*blockDim.x + threadIdx.x;
    if (t < DIMM)  g_h[t] = cls[t];
    if (t < 2)     g_coords[t] = 0.f;
    if (t < NPT*2) g_coords[2+t] = coords[t];
}

// ---------------- per-pair angle table position ----------------
__global__ void angpos_kernel() {
    int p = blockIdx.x*blockDim.x + threadIdx.x;
    if (p >= NPAIR) return;
    int i = p / NTOK, j = p - i*NTOK;
    float pos;
    if (i == j) {
        pos = (float)(TABN + 1);           // diag: dir = (0,0) special row
    } else {
        float dx = g_coords[2*i]   - g_coords[2*j];
        float dy = g_coords[2*i+1] - g_coords[2*j+1];
        float th = atan2f(dy, dx);
        pos = (th + PI_F) * ((float)TABN / (2.0f*PI_F));
        pos = fminf(fmaxf(pos, 0.f), (float)TABN);
    }
    g_angpos[p] = pos;
}

// ---------------- build CPB bias tables (both layers, grid.y selects) ----
__global__ void __launch_bounds__(256) cpb_table_kernel(
        const float* __restrict__ w1a, const float* __restrict__ b1a,
        const float* __restrict__ w2a, const float* __restrict__ b2a,
        float* __restrict__ outa,
        const float* __restrict__ w1b, const float* __restrict__ b1b,
        const float* __restrict__ w2b, const float* __restrict__ b2b,
        float* __restrict__ outb) {
    const float* w1 = blockIdx.y ? w1b : w1a;
    const float* b1 = blockIdx.y ? b1b : b1a;
    const float* w2 = blockIdx.y ? w2b : w2a;
    const float* b2 = blockIdx.y ? b2b : b2a;
    float*      out = blockIdx.y ? outb : outa;

    __shared__ float swx[CPBH], swy[CPBH], sbb[CPBH];
    __shared__ __align__(16) float sw2[CPBH*8];
    __shared__ float sred[8][32][9];
    int t = threadIdx.x;
    for (int c = t; c < CPBH; c += 256) {
        swx[c] = w1[c]; swy[c] = w1[CPBH + c]; sbb[c] = b1[c];
    }
    for (int c = t; c < CPBH*2; c += 256)
        *(float4*)(sw2 + c*4) = *(const float4*)(w2 + c*4);
    __syncthreads();

    int e = t & 31;
    int w = t >> 5;
    int idx = blockIdx.x*32 + e;
    float ux = 0.f, uy = 0.f;
    if (idx <= TABN) {
        float th = -PI_F + (2.0f*PI_F) * ((float)idx / (float)TABN);
        sincosf(th, &uy, &ux);
    }
    float acc[8] = {0.f,0.f,0.f,0.f,0.f,0.f,0.f,0.f};
    int c0 = w << 6;
    #pragma unroll 8
    for (int cc = 0; cc < 64; cc++) {
        int c = c0 + cc;
        float hv = fmaf(ux, swx[c], fmaf(uy, swy[c], sbb[c]));
        hv = fmaxf(hv, 0.f);
        float4 wa = *(const float4*)(sw2 + (c<<3));
        float4 wb = *(const float4*)(sw2 + (c<<3) + 4);
        acc[0] = fmaf(hv, wa.x, acc[0]);
        acc[1] = fmaf(hv, wa.y, acc[1]);
        acc[2] = fmaf(hv, wa.z, acc[2]);
        acc[3] = fmaf(hv, wa.w, acc[3]);
        acc[4] = fmaf(hv, wb.x, acc[4]);
        acc[5] = fmaf(hv, wb.y, acc[5]);
        acc[6] = fmaf(hv, wb.z, acc[6]);
        acc[7] = fmaf(hv, wb.w, acc[7]);
    }
    #pragma unroll
    for (int k = 0; k < 8; k++) sred[w][e][k] = acc[k];
    __syncthreads();

    int re = t >> 3, rk = t & 7;
    float s = 0.f;
    #pragma unroll
    for (int ww = 0; ww < 8; ww++) s += sred[ww][re][rk];
    int ridx = blockIdx.x*32 + re;
    if (ridx <= TABN + 2) {
        float v = (ridx == TABN + 2) ? 0.f : s + b2[rk];
        out[(size_t)ridx*8 + rk] = v;
    }
}

// ---------------- 32x64-tile fp32 GEMM, 128 threads, 4x4/thread -----------
// CTA-level split-K via blockIdx.z: slice z covers k in [z*K, (z+1)*K).
// With FLAG_RAW, raw partials go to C + z*M*ldc.
__global__ void __launch_bounds__(128) gemm_kernel(
        const float* __restrict__ A, int lda,
        const float* __restrict__ B, int ldb,
        const float* __restrict__ bias,
        float* __restrict__ C, int ldc,
        int M, int N, int K, int flags) {
    __shared__ __align__(16) float As[2][16][36];
    __shared__ __align__(16) float Bs[2][16][68];
    int t  = threadIdx.x;
    int m0 = blockIdx.y << 5, n0 = blockIdx.x << 6;
    int zi = blockIdx.z;
    const float* Az = A + (size_t)zi*K;           // k offset within row
    const float* Bz = B + (size_t)zi*K*ldb;
    float* Cz = C + (size_t)zi*M*ldc;             // partial-slice base (RAW)
    int arow = t >> 2, acol = (t & 3) << 2;       // A tile 32x16, float4/thread
    int brow = t >> 3, bcol = (t & 7) << 3;       // B tile 16x64, 2 float4/thread
    int tx = t & 15, ty = t >> 4;                 // out: 4 rows x 4 cols
    float acc[4][4] = {};

    bool aval = (m0 + arow) < M;
    const float* Aptr = Az + (size_t)(m0 + arow)*lda + acol;
    const float* Bptr = Bz + (size_t)brow*ldb + n0 + bcol;

    float4 ra  = aval ? *(const float4*)Aptr : make_float4(0.f,0.f,0.f,0.f);
    float4 rb0 = *(const float4*)Bptr;
    float4 rb1 = *(const float4*)(Bptr + 4);
    int buf = 0;
    As[0][acol  ][arow] = ra.x; As[0][acol+1][arow] = ra.y;
    As[0][acol+2][arow] = ra.z; As[0][acol+3][arow] = ra.w;
    *(float4*)&Bs[0][brow][bcol]   = rb0;
    *(float4*)&Bs[0][brow][bcol+4] = rb1;
    __syncthreads();

    for (int k0 = 16; ; k0 += 16) {
        bool more = (k0 < K);
        if (more) {
            ra  = aval ? *(const float4*)(Aptr + k0) : make_float4(0.f,0.f,0.f,0.f);
            rb0 = *(const float4*)(Bptr + (size_t)k0*ldb);
            rb1 = *(const float4*)(Bptr + (size_t)k0*ldb + 4);
        }
        #pragma unroll
        for (int k = 0; k < 16; k++) {
            float4 a = *(const float4*)&As[buf][k][ty<<2];
            float4 b = *(const float4*)&Bs[buf][k][tx<<2];
            acc[0][0] = fmaf(a.x, b.x, acc[0][0]);
            acc[0][1] = fmaf(a.x, b.y, acc[0][1]);
            acc[0][2] = fmaf(a.x, b.z, acc[0][2]);
            acc[0][3] = fmaf(a.x, b.w, acc[0][3]);
            acc[1][0] = fmaf(a.y, b.x, acc[1][0]);
            acc[1][1] = fmaf(a.y, b.y, acc[1][1]);
            acc[1][2] = fmaf(a.y, b.z, acc[1][2]);
            acc[1][3] = fmaf(a.y, b.w, acc[1][3]);
            acc[2][0] = fmaf(a.z, b.x, acc[2][0]);
            acc[2][1] = fmaf(a.z, b.y, acc[2][1]);
            acc[2][2] = fmaf(a.z, b.z, acc[2][2]);
            acc[2][3] = fmaf(a.z, b.w, acc[2][3]);
            acc[3][0] = fmaf(a.w, b.x, acc[3][0]);
            acc[3][1] = fmaf(a.w, b.y, acc[3][1]);
            acc[3][2] = fmaf(a.w, b.z, acc[3][2]);
            acc[3][3] = fmaf(a.w, b.w, acc[3][3]);
        }
        if (!more) break;
        buf ^= 1;
        As[buf][acol  ][arow] = ra.x; As[buf][acol+1][arow] = ra.y;
        As[buf][acol+2][arow] = ra.z; As[buf][acol+3][arow] = ra.w;
        *(float4*)&Bs[buf][brow][bcol]   = rb0;
        *(float4*)&Bs[buf][brow][bcol+4] = rb1;
        __syncthreads();
    }

    if (flags & FLAG_RAW) {
        #pragma unroll
        for (int i = 0; i < 4; i++) {
            int m = m0 + (ty<<2) + i;
            if (m >= M) break;
            *(float4*)(Cz + (size_t)m*ldc + n0 + (tx<<2)) =
                make_float4(acc[i][0], acc[i][1], acc[i][2], acc[i][3]);
        }
        return;
    }
    float4 bv = *(const float4*)(bias + n0 + (tx<<2));
    #pragma unroll
    for (int i = 0; i < 4; i++) {
        int m = m0 + (ty<<2) + i;
        if (m >= M) break;
        float4 v = make_float4(acc[i][0]+bv.x, acc[i][1]+bv.y,
                               acc[i][2]+bv.z, acc[i][3]+bv.w);
        if (flags & FLAG_RELU) {
            v.x = fmaxf(v.x,0.f); v.y = fmaxf(v.y,0.f);
            v.z = fmaxf(v.z,0.f); v.w = fmaxf(v.w,0.f);
        }
        float4* cp = (float4*)(C + (size_t)m*ldc + n0 + (tx<<2));
        if (flags & FLAG_ADD) {
            float4 o = *cp;
            v.x += o.x; v.y += o.y; v.z += o.z; v.w += o.w;
        }
        *cp = v;
    }
}

// ---------------- split-K reduce: C = op(sum_s part[s] + bias) ------------
__global__ void __launch_bounds__(256) reduce_kernel(
        const float* __restrict__ part, const float* __restrict__ bias,
        float* __restrict__ C, int MN, int N, int S, int flags) {
    int idx = (blockIdx.x*256 + threadIdx.x) << 2;
    if (idx >= MN) return;
    float4 v = *(const float4*)(part + idx);
    for (int s = 1; s < S; s++) {
        float4 p = *(const float4*)(part + (size_t)s*MN + idx);
        v.x += p.x; v.y += p.y; v.z += p.z; v.w += p.w;
    }
    float4 bv = *(const float4*)(bias + (idx % N));
    v.x += bv.x; v.y += bv.y; v.z += bv.z; v.w += bv.w;
    if (flags & FLAG_RELU) {
        v.x = fmaxf(v.x,0.f); v.y = fmaxf(v.y,0.f);
        v.z = fmaxf(v.z,0.f); v.w = fmaxf(v.w,0.f);
    }
    float4* cp = (float4*)(C + idx);
    if (flags & FLAG_ADD) {
        float4 o = *cp;
        v.x += o.x; v.y += o.y; v.z += o.z; v.w += o.w;
    }
    *cp = v;
}

// ---------------- layernorm (one block per row) ----------------
__global__ void ln_kernel(const float* __restrict__ x, float* __restrict__ y,
                          const float* __restrict__ g, const float* __restrict__ b) {
    int row = blockIdx.x, t = threadIdx.x;     // 256 threads
    const float* xr = x + (size_t)row*DIMM;
    float v0 = xr[t], v1 = xr[t+256];
    float2 s = blockReduce2_256(v0+v1, v0*v0+v1*v1);
    float mean = s.x * (1.f/512.f);
    float inv  = rsqrtf(s.y*(1.f/512.f) - mean*mean + 1e-5f);
    y[(size_t)row*DIMM + t]       = (v0-mean)*inv*g[t]     + b[t];
    y[(size_t)row*DIMM + t + 256] = (v1-mean)*inv*g[t+256] + b[t+256];
}

// ---------------- QK^T scores + fused CPB bias ----------------
__global__ void __launch_bounds__(128) scores_kernel(const float* __restrict__ tab) {
    __shared__ __align__(16) float Qs[64][36];   // [d][i]
    __shared__ __align__(16) float Ks[64][68];   // [d][j]
    int h  = blockIdx.z;
    int i0 = blockIdx.y << 5, j0 = blockIdx.x << 6;
    int t  = threadIdx.x;

    {
        int r = t >> 2, c = (t & 3) << 4;
        const float* qp = g_qkv + (size_t)(i0+r)*QKV3 + h*HDIM + c;
        bool v = (i0 + r) < NTOK;
        #pragma unroll
        for (int q = 0; q < 4; q++) {
            float4 x = v ? *(const float4*)(qp + (q<<2)) : make_float4(0.f,0.f,0.f,0.f);
            int d = c + (q<<2);
            Qs[d  ][r] = x.x; Qs[d+1][r] = x.y;
            Qs[d+2][r] = x.z; Qs[d+3][r] = x.w;
        }
    }
    {
        int r = t >> 1, c = (t & 1) << 5;
        const float* kp = g_qkv + (size_t)(j0+r)*QKV3 + DIMM + h*HDIM + c;
        bool v = (j0 + r) < NTOK;
        #pragma unroll
        for (int q = 0; q < 8; q++) {
            float4 x = v ? *(const float4*)(kp + (q<<2)) : make_float4(0.f,0.f,0.f,0.f);
            int d = c + (q<<2);
            Ks[d  ][r] = x.x; Ks[d+1][r] = x.y;
            Ks[d+2][r] = x.z; Ks[d+3][r] = x.w;
        }
    }
    __syncthreads();

    int tx = t & 15, ty = t >> 4;
    float acc[4][4] = {};
    #pragma unroll 8
    for (int d = 0; d < 64; d++) {
        float4 a = *(const float4*)&Qs[d][ty<<2];
        float4 b = *(const float4*)&Ks[d][tx<<2];
        acc[0][0] = fmaf(a.x, b.x, acc[0][0]);
        acc[0][1] = fmaf(a.x, b.y, acc[0][1]);
        acc[0][2] = fmaf(a.x, b.z, acc[0][2]);
        acc[0][3] = fmaf(a.x, b.w, acc[0][3]);
        acc[1][0] = fmaf(a.y, b.x, acc[1][0]);
        acc[1][1] = fmaf(a.y, b.y, acc[1][1]);
        acc[1][2] = fmaf(a.y, b.z, acc[1][2]);
        acc[1][3] = fmaf(a.y, b.w, acc[1][3]);
        acc[2][0] = fmaf(a.z, b.x, acc[2][0]);
        acc[2][1] = fmaf(a.z, b.y, acc[2][1]);
        acc[2][2] = fmaf(a.z, b.z, acc[2][2]);
        acc[2][3] = fmaf(a.z, b.w, acc[2][3]);
        acc[3][0] = fmaf(a.w, b.x, acc[3][0]);
        acc[3][1] = fmaf(a.w, b.y, acc[3][1]);
        acc[3][2] = fmaf(a.w, b.z, acc[3][2]);
        acc[3][3] = fmaf(a.w, b.w, acc[3][3]);
    }

    #pragma unroll
    for (int qi = 0; qi < 4; qi++) {
        int i = i0 + (ty<<2) + qi;
        if (i >= NTOK) break;
        #pragma unroll
        for (int qj = 0; qj < 4; qj++) {
            int j = j0 + (tx<<2) + qj;
            if (j < NTOK) {
                size_t p = (size_t)i*NTOK + j;
                float pos = g_angpos[p];
                int   ip  = (int)pos;
                float f   = pos - (float)ip;
                const float* r0 = tab + (size_t)ip*8 + h;
                float bias = r0[0] + f*(r0[8] - r0[0]);
                g_attn[(size_t)h*NTOK*NTOK + p] = fmaf(0.125f, acc[qi][qj], bias);
            }
        }
    }
}

// ---------------- fused softmax + attn@V (per-head, 32 i-rows) ------------
__global__ void __launch_bounds__(256) softav_kernel() {
    __shared__ float sa[32][33];
    __shared__ __align__(16) float sv[32][68];
    __shared__ float smx[32], sinv[32];
    int h  = blockIdx.y;
    int i0 = blockIdx.x << 5;
    int t  = threadIdx.x;

    {
        int row = t >> 3, k8 = t & 7;
        int gi  = i0 + row;
        int cgi = gi < NTOK ? gi : NTOK - 1;
        const float* arow = g_attn + ((size_t)h*NTOK + cgi)*NTOK;
        float m = -1e30f;
        for (int j = k8; j < NTOK; j += 8) m = fmaxf(m, arow[j]);
        #pragma unroll
        for (int o = 1; o < 8; o <<= 1)
            m = fmaxf(m, __shfl_xor_sync(0xffffffffu, m, o));
        float s = 0.f;
        for (int j = k8; j < NTOK; j += 8) s += __expf(arow[j] - m);
        #pragma unroll
        for (int o = 1; o < 8; o <<= 1)
            s += __shfl_xor_sync(0xffffffffu, s, o);
        if (k8 == 0) { smx[row] = m; sinv[row] = 1.f / s; }
    }
    __syncthreads();

    int tx = t & 15, ty = t >> 4;
    int d4 = tx << 2;
    int ar = t >> 3, ac = (t & 7) << 2;
    int vr = t >> 3, vc = (t & 7) << 3;
    float mrow = smx[ar];
    float acc[2][4] = {};
    for (int j0 = 0; j0 < NTOK; j0 += 32) {
        #pragma unroll
        for (int q = 0; q < 4; q++) {
            int i = i0 + ar, j = j0 + ac + q;
            float e = 0.f;
            if (i < NTOK && j < NTOK)
                e = __expf(g_attn[((size_t)h*NTOK + i)*NTOK + j] - mrow);
            sa[ar][ac+q] = e;
        }
        {
            const float* vp = g_qkv + (size_t)(j0+vr)*QKV3 + 2*DIMM + h*HDIM + vc;
            bool vi = (j0 + vr < NTOK);
            float4 z = make_float4(0.f,0.f,0.f,0.f);
            float4 v0 = vi ? *(const float4*)vp       : z;
            float4 v1 = vi ? *(const float4*)(vp + 4) : z;
            *(float4*)&sv[vr][vc]   = v0;
            *(float4*)&sv[vr][vc+4] = v1;
        }
        __syncthreads();
        #pragma unroll
        for (int j = 0; j < 32; j++) {
            float4 vv = *(const float4*)&sv[j][d4];
            float a0 = sa[ty][j], a1 = sa[ty+16][j];
            acc[0][0] = fmaf(a0, vv.x, acc[0][0]);
            acc[0][1] = fmaf(a0, vv.y, acc[0][1]);
            acc[0][2] = fmaf(a0, vv.z, acc[0][2]);
            acc[0][3] = fmaf(a0, vv.w, acc[0][3]);
            acc[1][0] = fmaf(a1, vv.x, acc[1][0]);
            acc[1][1] = fmaf(a1, vv.y, acc[1][1]);
            acc[1][2] = fmaf(a1, vv.z, acc[1][2]);
            acc[1][3] = fmaf(a1, vv.w, acc[1][3]);
        }
        __syncthreads();
    }
    #pragma unroll
    for (int q = 0; q < 2; q++) {
        int i = i0 + ty + (q<<4);
        if (i < NTOK) {
            float inv = sinv[ty + (q<<4)];
            *(float4*)(g_ao + (size_t)i*DIMM + h*HDIM + d4) =
                make_float4(acc[q][0]*inv, acc[q][1]*inv,
                            acc[q][2]*inv, acc[q][3]*inv);
        }
    }
}

// ---------------- final: LN(row 0) -> fc2 -> out[2] ----------------
__global__ void final_kernel(const float* __restrict__ g, const float* __restrict__ b,
                             const float* __restrict__ w, const float* __restrict__ bias,
                             float* __restrict__ out) {
    int t = threadIdx.x;                  // 256 threads
    float v0 = g_h[t], v1 = g_h[t+256];
    float2 s = blockReduce2_256(v0+v1, v0*v0+v1*v1);
    float mean = s.x * (1.f/512.f);
    float inv  = rsqrtf(s.y*(1.f/512.f) - mean*mean + 1e-5f);
    float l0 = (v0-mean)*inv*g[t]     + b[t];
    float l1 = (v1-mean)*inv*g[t+256] + b[t+256];
    float p0 = l0*w[t*2]   + l1*w[(t+256)*2];
    float p1 = l0*w[t*2+1] + l1*w[(t+256)*2+1];
    float2 sp = blockReduce2_256(p0, p1);
    if (t == 0) { out[0] = sp.x + bias[0]; out[1] = sp.y + bias[1]; }
}

// ---------------- launch ----------------
extern "C" void kernel_launch(void* const* d_in, const int* in_sizes, int n_in,
                              void* d_out, int out_size) {
    const float* h_in   = (const float*)d_in[0];
    const float* coords = (const float*)d_in[1];
    const float* fc1_w  = (const float*)d_in[2];
    const float* fc1_b  = (const float*)d_in[3];
    const float* cls    = (const float*)d_in[4];
    const float* norm_g = (const float*)d_in[25];
    const float* norm_b = (const float*)d_in[26];
    const float* fc2_w  = (const float*)d_in[27];
    const float* fc2_b  = (const float*)d_in[28];

    float *p_h, *p_ln, *p_qkv, *p_ao, *p_part, *p_tab[2];
    cudaGetSymbolAddress((void**)&p_h,      g_h);
    cudaGetSymbolAddress((void**)&p_ln,     g_ln);
    cudaGetSymbolAddress((void**)&p_qkv,    g_qkv);
    cudaGetSymbolAddress((void**)&p_ao,     g_ao);
    cudaGetSymbolAddress((void**)&p_part,   g_part);
    cudaGetSymbolAddress((void**)&p_tab[0], g_table0);
    cudaGetSymbolAddress((void**)&p_tab[1], g_table1);

    setup_kernel<<<4, 256>>>(cls, coords);
    angpos_kernel<<<(NPAIR + 255)/256, 256>>>();
    cpb_table_kernel<<<dim3((TABN + 3 + 31)/32, 2), 256>>>(
        (const float*)d_in[7],  (const float*)d_in[8],
        (const float*)d_in[9],  (const float*)d_in[10], p_tab[0],
        (const float*)d_in[17], (const float*)d_in[18],
        (const float*)d_in[19], (const float*)d_in[20], p_tab[1]);

    // fc1: 32x64 tile, split-K x4 (K=1024 -> 4x256), reduce+bias+relu
    gemm_kernel<<<dim3(DIMM/64, (NPT+31)/32, 4), 128>>>(
        h_in, 1024, fc1_w, DIMM, (const float*)0,
        p_part, DIMM, NPT, DIMM, 256, FLAG_RAW);
    reduce_kernel<<<(NPT*DIMM/4 + 255)/256, 256>>>(
        p_part, fc1_b, p_h + DIMM, NPT*DIMM, DIMM, 4, FLAG_RELU);

    for (int L = 0; L < 2; L++) {
        const float* lp[10];
        for (int q = 0; q < 10; q++) lp[q] = (const float*)d_in[5 + L*10 + q];
        const float* ln_g   = lp[0]; const float* ln_b   = lp[1];
        const float* qkv_w  = lp[6]; const float* qkv_b  = lp[7];
        const float* proj_w = lp[8]; const float* proj_b = lp[9];

        ln_kernel<<<NTOK, 256>>>(p_h, p_ln, ln_g, ln_b);
        // qkv: split-K x2 (K=512 -> 2x256), reduce+bias
        gemm_kernel<<<dim3(QKV3/64, (NTOK+31)/32, 2), 128>>>(
            p_ln, DIMM, qkv_w, QKV3, (const float*)0,
            p_part, QKV3, NTOK, QKV3, 256, FLAG_RAW);
        reduce_kernel<<<(NTOK*QKV3/4 + 255)/256, 256>>>(
            p_part, qkv_b, p_qkv, NTOK*QKV3, QKV3, 2, 0);
        scores_kernel<<<dim3(7, 13, NHEAD), 128>>>(p_tab[L]);
        softav_kernel<<<dim3(13, NHEAD), 256>>>();
        // proj: split-K x4 (K=512 -> 4x128), reduce+bias+residual
        gemm_kernel<<<dim3(DIMM/64, (NTOK+31)/32, 4), 128>>>(
            p_ao, DIMM, proj_w, DIMM, (const float*)0,
            p_part, DIMM, NTOK, DIMM, 128, FLAG_RAW);
        reduce_kernel<<<(NTOK*DIMM/4 + 255)/256, 256>>>(
            p_part, proj_b, p_h, NTOK*DIMM, DIMM, 4, FLAG_ADD);
    }

    final_kernel<<<1, 256>>>(norm_g, norm_b, fc2_w, fc2_b, (float*)d_out);
}